// round 2
// baseline (speedup 1.0000x reference)
#include <cuda_runtime.h>

// ---------------- problem constants ----------------
#define BB 64
#define NN 16
#define PP 20
#define NBCLS 30
#define CC 1024
#define FF 14
#define SPAT (FF*FF)     // 196
#define S_TOT (BB + BB*NN)   // 1088
#define C1 512
#define C2 256
#define CD 2304          // 256*9
#define FC1DIM 1024

// ---------------- static device scratch ----------------
__device__ float g_fmapT[BB*SPAT*CC];        // [b][y*14+x][c]
__device__ float g_roi[S_TOT*9*CC];          // [s][k][ci]
__device__ float g_wt1[CC*9*C1];             // [ci][k][co]
__device__ float g_out1[S_TOT*9*C1];         // [s][k][co]
__device__ float g_wt2[C1*9*C2];             // [ci][k][co]
__device__ float g_out2[S_TOT*9*C2];         // [s][k][co]
__device__ float g_w1d[CD*3*CD];             // [ci][t][co]
__device__ float g_bpcb[PP*CD*BB];           // [p][c][b]
__device__ float g_x1d[PP*CD*BB];            // [p][c][b]
__device__ float g_feats[BB*NN*CD];          // [r][c]
__device__ float g_h[BB*NN*FC1DIM];          // [r][j]
__device__ float g_scale1[C1], g_shift1[C1];
__device__ float g_scale2[C2], g_shift2[C2];

// ---------------- BN folding ----------------
__global__ void bnfold_kernel(const float* g1, const float* b1, const float* m1, const float* v1,
                              const float* g2, const float* b2, const float* m2, const float* v2) {
    int t = blockIdx.x * blockDim.x + threadIdx.x;
    if (t < C1) {
        float s = g1[t] * rsqrtf(v1[t] + 1e-5f);
        g_scale1[t] = s;
        g_shift1[t] = b1[t] - m1[t] * s;
    } else if (t < C1 + C2) {
        int i = t - C1;
        float s = g2[i] * rsqrtf(v2[i] + 1e-5f);
        g_scale2[i] = s;
        g_shift2[i] = b2[i] - m2[i] * s;
    }
}

// ---------------- fmap transpose to channel-last ----------------
__global__ void tfmap_kernel(const float* __restrict__ fmap) {
    int pos = blockIdx.x;            // b*196 + yx
    int b = pos / SPAT, yx = pos % SPAT;
    for (int c = threadIdx.x; c < CC; c += blockDim.x)
        g_fmapT[pos * CC + c] = fmap[(b * CC + c) * SPAT + yx];
}

// ---------------- conv weight transpose [co][ci][k] -> [ci][k][co] ----------------
__global__ void twconv_kernel(const float* __restrict__ w, float* __restrict__ out,
                              int cin, int cout) {
    int cik = blockIdx.x;            // ci*9 + k
    int ci = cik / 9, k = cik % 9;
    for (int co = threadIdx.x; co < cout; co += blockDim.x)
        out[cik * cout + co] = w[(co * cin + ci) * 9 + k];
}

__global__ void tw1d_kernel(const float* __restrict__ w) {
    int cit = blockIdx.x;            // ci*3 + t
    int ci = cit / 3, t = cit % 3;
    for (int co = threadIdx.x; co < CD; co += blockDim.x)
        g_w1d[cit * CD + co] = w[(co * CD + ci) * 3 + t];
}

// ---------------- roi align ----------------
__global__ void roialign_kernel(const float* __restrict__ boxes) {
    __shared__ float swy[6], swx[6];
    __shared__ int sy0[6], sy1[6], sx0[6], sx1[6];
    int s = blockIdx.x;
    if (threadIdx.x == 0) {
        float x1, y1, x2, y2;
        if (s < BB) { x1 = 0.f; y1 = 0.f; x2 = (float)FF; y2 = (float)FF; }
        else {
            const float* bx = boxes + (size_t)(s - BB) * 4;
            x1 = bx[0]; y1 = bx[1]; x2 = bx[2]; y2 = bx[3];
        }
        float rw = fmaxf(x2 - x1, 1.f), rh = fmaxf(y2 - y1, 1.f);
        float scy = rh / 3.0f, scx = rw / 3.0f;
        for (int i = 0; i < 6; i++) {
            float pos = ((float)i + 0.5f) * 0.5f;
            float ys = fminf(fmaxf(y1 + pos * scy, 0.f), 13.f);
            float xs = fminf(fmaxf(x1 + pos * scx, 0.f), 13.f);
            float y0 = floorf(ys), x0 = floorf(xs);
            int y0i = (int)y0, x0i = (int)x0;
            sy0[i] = y0i; sx0[i] = x0i;
            sy1[i] = min(y0i + 1, 13); sx1[i] = min(x0i + 1, 13);
            swy[i] = ys - y0; swx[i] = xs - x0;
        }
    }
    __syncthreads();
    int b = (s < BB) ? s : (s - BB) / NN;
    const float* fm = g_fmapT + (size_t)b * SPAT * CC;
    for (int c = threadIdx.x; c < CC; c += blockDim.x) {
        float acc[9];
        #pragma unroll
        for (int k = 0; k < 9; k++) acc[k] = 0.f;
        #pragma unroll
        for (int sy = 0; sy < 6; sy++) {
            float wy = swy[sy];
            int y0 = sy0[sy], y1 = sy1[sy];
            #pragma unroll
            for (int sx = 0; sx < 6; sx++) {
                float wx = swx[sx];
                int x0 = sx0[sx], x1 = sx1[sx];
                float v00 = fm[(y0 * FF + x0) * CC + c];
                float v01 = fm[(y0 * FF + x1) * CC + c];
                float v10 = fm[(y1 * FF + x0) * CC + c];
                float v11 = fm[(y1 * FF + x1) * CC + c];
                float v = v00 * (1.f - wy) * (1.f - wx) + v01 * (1.f - wy) * wx
                        + v10 * wy * (1.f - wx) + v11 * wy * wx;
                acc[(sy >> 1) * 3 + (sx >> 1)] += v;
            }
        }
        #pragma unroll
        for (int k = 0; k < 9; k++)
            g_roi[((size_t)s * 9 + k) * CC + c] = acc[k] * 0.25f;
    }
}

// ---------------- 3x3 SAME conv on 3x3 spatial, fused BN + leaky ----------------
// input  [s][k][CIN], weight [ci][k][COUT], output [s][k][COUT]
// CTA: 4 samples x 128 out channels. 256 threads.
template<int CIN, int COUT>
__global__ void conv3x3_kernel(const float* __restrict__ in,
                               const float* __restrict__ wt,
                               const float* __restrict__ scale,
                               const float* __restrict__ shift,
                               float* __restrict__ out) {
    extern __shared__ float sIn[];   // [4][9][CIN]
    int s0 = blockIdx.x * 4;
    int co = blockIdx.y * 128 + (threadIdx.x & 127);
    int sg = threadIdx.x >> 7;       // 0 or 1

    // cooperative vectorized load of 4 samples of input
    const int total4 = 4 * 9 * CIN / 4;
    const float4* gIn4 = (const float4*)(in + (size_t)s0 * 9 * CIN);
    float4* sIn4 = (float4*)sIn;
    for (int i = threadIdx.x; i < total4; i += 256) sIn4[i] = gIn4[i];
    __syncthreads();

    float acc[2][9];
    #pragma unroll
    for (int sm = 0; sm < 2; sm++)
        #pragma unroll
        for (int k = 0; k < 9; k++) acc[sm][k] = 0.f;

    for (int ci = 0; ci < CIN; ci++) {
        float wv[9];
        const float* wp = wt + ((size_t)ci * 9) * COUT + co;
        #pragma unroll
        for (int k = 0; k < 9; k++) wv[k] = wp[(size_t)k * COUT];
        #pragma unroll
        for (int sm = 0; sm < 2; sm++) {
            int smp = sg * 2 + sm;
            float v[9];
            #pragma unroll
            for (int j = 0; j < 9; j++) v[j] = sIn[(smp * 9 + j) * CIN + ci];
            #pragma unroll
            for (int iy = 0; iy < 3; iy++) {
                #pragma unroll
                for (int ix = 0; ix < 3; ix++) {
                    float x = v[iy * 3 + ix];
                    #pragma unroll
                    for (int ky = 0; ky < 3; ky++) {
                        int oy = iy + 1 - ky;
                        if (oy < 0 || oy > 2) continue;
                        #pragma unroll
                        for (int kx = 0; kx < 3; kx++) {
                            int ox = ix + 1 - kx;
                            if (ox < 0 || ox > 2) continue;
                            acc[sm][oy * 3 + ox] = fmaf(x, wv[ky * 3 + kx], acc[sm][oy * 3 + ox]);
                        }
                    }
                }
            }
        }
    }

    float sc = scale[co], sh = shift[co];
    #pragma unroll
    for (int sm = 0; sm < 2; sm++) {
        int s = s0 + sg * 2 + sm;
        #pragma unroll
        for (int k = 0; k < 9; k++) {
            float v = acc[sm][k] * sc + sh;
            v = v > 0.f ? v : 0.1f * v;
            out[((size_t)s * 9 + k) * COUT + co] = v;
        }
    }
}

// ---------------- behavior build: broadcast g_feat + scatter-add i_feat ----------------
__global__ void buildbehavior_kernel(const int* __restrict__ person_idx) {
    int p = blockIdx.x / BB, b = blockIdx.x % BB;
    __shared__ int pid[NN];
    if (threadIdx.x < NN) pid[threadIdx.x] = person_idx[b * NN + threadIdx.x];
    __syncthreads();
    for (int c = threadIdx.x; c < CD; c += blockDim.x) {
        int co = c / 9, k = c % 9;
        float v = g_out2[((size_t)b * 9 + k) * C2 + co];
        #pragma unroll
        for (int n = 0; n < NN; n++)
            if (pid[n] == p)
                v += g_out2[((size_t)(BB + b * NN + n) * 9 + k) * C2 + co];
        g_bpcb[((size_t)p * CD + c) * BB + b] = v;
    }
}

// ---------------- conv1d over batch axis (len 64, k=3, SAME) ----------------
__global__ void conv1d_kernel(const float* __restrict__ bias) {
    __shared__ float sIn[128 * 66];  // [ci][b+1], padded ends
    int p = blockIdx.x;
    int co = blockIdx.y * 128 + (threadIdx.x & 127);
    int sg = threadIdx.x >> 7;
    int bb = sg * 32;
    float acc[32];
    #pragma unroll
    for (int j = 0; j < 32; j++) acc[j] = 0.f;

    for (int ci0 = 0; ci0 < CD; ci0 += 128) {
        __syncthreads();
        for (int i = threadIdx.x; i < 128 * 64; i += 256) {
            int ci = i >> 6, b = i & 63;
            sIn[ci * 66 + b + 1] = g_bpcb[((size_t)p * CD + ci0 + ci) * BB + b];
        }
        for (int i = threadIdx.x; i < 128; i += 256) {
            sIn[i * 66] = 0.f;
            sIn[i * 66 + 65] = 0.f;
        }
        __syncthreads();
        for (int ci = 0; ci < 128; ci++) {
            const float* wp = g_w1d + ((size_t)(ci0 + ci) * 3) * CD + co;
            float w0 = wp[0], w1 = wp[CD], w2 = wp[2 * CD];
            const float* ip = sIn + ci * 66 + bb;
            float v0 = ip[0], v1 = ip[1];
            #pragma unroll
            for (int j = 0; j < 32; j++) {
                float v2 = ip[j + 2];
                acc[j] = fmaf(w0, v0, acc[j]);
                acc[j] = fmaf(w1, v1, acc[j]);
                acc[j] = fmaf(w2, v2, acc[j]);
                v0 = v1; v1 = v2;
            }
        }
    }
    float bv = bias[co];
    #pragma unroll
    for (int j = 0; j < 32; j++)
        g_x1d[((size_t)p * CD + co) * BB + bb + j] = acc[j] + bv;
}

// ---------------- gather feats[r][c] = x1d[pidx(r)][c][b(r)] ----------------
__global__ void gatherfeats_kernel(const int* __restrict__ person_idx) {
    int r = blockIdx.x;
    int b = r >> 4;
    int p = person_idx[r];
    for (int c = threadIdx.x; c < CD; c += blockDim.x)
        g_feats[(size_t)r * CD + c] = g_x1d[((size_t)p * CD + c) * BB + b];
}

// ---------------- fc1: [1024 x 2304] @ [2304 x 1024] + bias, relu ----------------
__global__ void fc1_kernel(const float* __restrict__ w, const float* __restrict__ bias) {
    __shared__ float As[16][64];
    __shared__ float Bs[16][64];
    int r0 = blockIdx.y * 64, j0 = blockIdx.x * 64;
    int tid = threadIdx.x;
    int ty = tid / 16, tx = tid % 16;
    float acc[4][4];
    #pragma unroll
    for (int i = 0; i < 4; i++)
        #pragma unroll
        for (int j = 0; j < 4; j++) acc[i][j] = 0.f;

    for (int k0 = 0; k0 < CD; k0 += 16) {
        __syncthreads();
        for (int i = tid; i < 64 * 16; i += 256) {
            int rr = i / 16, kk = i % 16;
            As[kk][rr] = g_feats[(size_t)(r0 + rr) * CD + k0 + kk];
        }
        for (int i = tid; i < 16 * 64; i += 256) {
            int kk = i / 64, jj = i % 64;
            Bs[kk][jj] = w[(size_t)(k0 + kk) * FC1DIM + j0 + jj];
        }
        __syncthreads();
        #pragma unroll
        for (int k = 0; k < 16; k++) {
            float a[4], bv[4];
            #pragma unroll
            for (int i = 0; i < 4; i++) a[i] = As[k][ty * 4 + i];
            #pragma unroll
            for (int j = 0; j < 4; j++) bv[j] = Bs[k][tx * 4 + j];
            #pragma unroll
            for (int i = 0; i < 4; i++)
                #pragma unroll
                for (int j = 0; j < 4; j++)
                    acc[i][j] = fmaf(a[i], bv[j], acc[i][j]);
        }
    }
    #pragma unroll
    for (int i = 0; i < 4; i++)
        #pragma unroll
        for (int j = 0; j < 4; j++) {
            float v = acc[i][j] + bias[j0 + tx * 4 + j];
            g_h[(size_t)(r0 + ty * 4 + i) * FC1DIM + j0 + tx * 4 + j] = v > 0.f ? v : 0.f;
        }
}

// ---------------- fc2: [1024 x 1024] @ [1024 x 30] + bias ----------------
__global__ void fc2_kernel(const float* __restrict__ w, const float* __restrict__ bias,
                           float* __restrict__ out) {
    int r = blockIdx.x;
    int lane = threadIdx.x;
    float acc = 0.f;
    for (int k = 0; k < FC1DIM; k++) {
        float h = g_h[(size_t)r * FC1DIM + k];
        if (lane < NBCLS) acc = fmaf(h, w[k * NBCLS + lane], acc);
    }
    if (lane < NBCLS) out[r * NBCLS + lane] = acc + bias[lane];
}

// ---------------- launch ----------------
extern "C" void kernel_launch(void* const* d_in, const int* in_sizes, int n_in,
                              void* d_out, int out_size) {
    const float* fmap      = (const float*)d_in[0];
    const float* boxes     = (const float*)d_in[1];
    const int*   person_idx= (const int*)  d_in[2];
    const float* conv1_w   = (const float*)d_in[3];
    const float* bn1_g     = (const float*)d_in[4];
    const float* bn1_b     = (const float*)d_in[5];
    const float* bn1_m     = (const float*)d_in[6];
    const float* bn1_v     = (const float*)d_in[7];
    const float* conv2_w   = (const float*)d_in[8];
    const float* bn2_g     = (const float*)d_in[9];
    const float* bn2_b     = (const float*)d_in[10];
    const float* bn2_m     = (const float*)d_in[11];
    const float* bn2_v     = (const float*)d_in[12];
    const float* conv1d_w  = (const float*)d_in[13];
    const float* conv1d_b  = (const float*)d_in[14];
    const float* fc1_w     = (const float*)d_in[15];
    const float* fc1_b     = (const float*)d_in[16];
    const float* fc2_w     = (const float*)d_in[17];
    const float* fc2_b     = (const float*)d_in[18];
    float* out = (float*)d_out;

    // resolve scratch symbols used as kernel args
    void *p_roi, *p_wt1, *p_out1, *p_wt2, *p_out2, *p_sc1, *p_sh1, *p_sc2, *p_sh2;
    cudaGetSymbolAddress(&p_roi,  g_roi);
    cudaGetSymbolAddress(&p_wt1,  g_wt1);
    cudaGetSymbolAddress(&p_out1, g_out1);
    cudaGetSymbolAddress(&p_wt2,  g_wt2);
    cudaGetSymbolAddress(&p_out2, g_out2);
    cudaGetSymbolAddress(&p_sc1,  g_scale1);
    cudaGetSymbolAddress(&p_sh1,  g_shift1);
    cudaGetSymbolAddress(&p_sc2,  g_scale2);
    cudaGetSymbolAddress(&p_sh2,  g_shift2);

    // allow large dynamic smem on the conv kernels
    cudaFuncSetAttribute(conv3x3_kernel<CC, C1>,
                         cudaFuncAttributeMaxDynamicSharedMemorySize, 4 * 9 * CC * 4);
    cudaFuncSetAttribute(conv3x3_kernel<C1, C2>,
                         cudaFuncAttributeMaxDynamicSharedMemorySize, 4 * 9 * C1 * 4);

    // 1. BN fold
    bnfold_kernel<<<3, 256>>>(bn1_g, bn1_b, bn1_m, bn1_v, bn2_g, bn2_b, bn2_m, bn2_v);
    // 2. transposes
    tfmap_kernel<<<BB * SPAT, 256>>>(fmap);
    twconv_kernel<<<CC * 9, 256>>>(conv1_w, (float*)p_wt1, CC, C1);
    twconv_kernel<<<C1 * 9, 256>>>(conv2_w, (float*)p_wt2, C1, C2);
    tw1d_kernel<<<CD * 3, 256>>>(conv1d_w);
    // 3. roi align (g rois + i rois)
    roialign_kernel<<<S_TOT, 256>>>(boxes);
    // 4. conv1 + bn + leaky
    conv3x3_kernel<CC, C1><<<dim3(S_TOT / 4, C1 / 128), 256, 4 * 9 * CC * 4>>>(
        (const float*)p_roi, (const float*)p_wt1,
        (const float*)p_sc1, (const float*)p_sh1, (float*)p_out1);
    // 5. conv2 + bn + leaky
    conv3x3_kernel<C1, C2><<<dim3(S_TOT / 4, C2 / 128), 256, 4 * 9 * C1 * 4>>>(
        (const float*)p_out1, (const float*)p_wt2,
        (const float*)p_sc2, (const float*)p_sh2, (float*)p_out2);
    // 6. behavior tensor [p][c][b]
    buildbehavior_kernel<<<PP * BB, 256>>>(person_idx);
    // 7. conv1d over batch axis
    conv1d_kernel<<<dim3(PP, CD / 128), 256>>>(conv1d_b);
    // 8. gather person features
    gatherfeats_kernel<<<BB * NN, 256>>>(person_idx);
    // 9. fc1 + relu
    fc1_kernel<<<dim3(FC1DIM / 64, (BB * NN) / 64), 256>>>(fc1_w, fc1_b);
    // 10. fc2 -> output
    fc2_kernel<<<BB * NN, 32>>>(fc2_w, fc2_b, out);
}

// round 4
// speedup vs baseline: 4.8676x; 4.8676x over previous
#include <cuda_runtime.h>
#include <cuda_fp16.h>
#include <cstdint>

// ---------------- problem constants ----------------
#define BB 64
#define NN 16
#define PP 20
#define NBCLS 30
#define CC 1024
#define FF 14
#define SPAT 196
#define S_TOT 1088
#define S_PAD 1152          // padded to multiple of 128
#define C1 512
#define C2 256
#define CD 2304
#define K1 (9*CC)           // 9216
#define N1 (9*C1)           // 4608
#define K2 (9*C1)           // 4608
#define N2 (9*C2)           // 2304
#define K1D (3*CD)          // 6912
#define M1D (PP*BB)         // 1280
#define FC1DIM 1024

// ---------------- static device scratch ----------------
__device__ float  g_fmapT[BB*SPAT*CC];            // [b][yx][c]
__device__ __half g_roiH[(size_t)S_PAD*K1];       // A of conv1  [s][ki*CC+ci]
__device__ __half g_BT1[(size_t)N1*K1];           // conv1 expanded weights [n][k]
__device__ __half g_out1h[(size_t)S_PAD*N1];      // conv1 out / A of conv2
__device__ __half g_BT2[(size_t)N2*K2];           // conv2 expanded weights
__device__ __half g_out2h[(size_t)S_PAD*N2];      // conv2 out [s][ko*C2+co]
__device__ __half g_A1d[(size_t)M1D*K1D];         // im2col for conv1d [p*64+b][t*CD+c]
__device__ __half g_BT1d[(size_t)CD*K1D];         // conv1d weights [co][t*CD+ci]
__device__ __half g_x1dh[(size_t)M1D*CD];         // conv1d out [p*64+b][co]
__device__ __half g_BTf1[(size_t)FC1DIM*CD];      // fc1 weights [n][k]
__device__ __half g_hh[(size_t)BB*NN*FC1DIM];     // fc1 out
__device__ float  g_scale1[C1], g_shift1[C1];
__device__ float  g_scale2[C2], g_shift2[C2];
__device__ int    g_rowmap[BB*NN];

// ---------------- BN folding ----------------
__global__ void bnfold_kernel(const float* g1, const float* b1, const float* m1, const float* v1,
                              const float* g2, const float* b2, const float* m2, const float* v2) {
    int t = blockIdx.x * blockDim.x + threadIdx.x;
    if (t < C1) {
        float s = g1[t] * rsqrtf(v1[t] + 1e-5f);
        g_scale1[t] = s;
        g_shift1[t] = b1[t] - m1[t] * s;
    } else if (t < C1 + C2) {
        int i = t - C1;
        float s = g2[i] * rsqrtf(v2[i] + 1e-5f);
        g_scale2[i] = s;
        g_shift2[i] = b2[i] - m2[i] * s;
    }
}

// ---------------- fmap transpose to channel-last ----------------
__global__ void tfmap_kernel(const float* __restrict__ fmap) {
    int pos = blockIdx.x;            // b*196 + yx
    int b = pos / SPAT, yx = pos % SPAT;
    for (int c = threadIdx.x; c < CC; c += blockDim.x)
        g_fmapT[(size_t)pos * CC + c] = fmap[((size_t)b * CC + c) * SPAT + yx];
}

// ---------------- expanded conv weights: BT[n][k], n=ko*COUT+co, k=ki*CIN+ci ----------------
__global__ void expand_conv_w(const float* __restrict__ w, __half* __restrict__ BT,
                              int CIN, int COUT) {
    int n = blockIdx.x;
    int co = n % COUT, ko = n / COUT;
    int oy = ko / 3, ox = ko % 3;
    int K = 9 * CIN;
    for (int k = threadIdx.x; k < K; k += blockDim.x) {
        int ki = k / CIN, ci = k % CIN;
        int ky = ki / 3 - oy + 1, kx = ki % 3 - ox + 1;
        float v = 0.f;
        if ((unsigned)ky < 3u && (unsigned)kx < 3u)
            v = w[((size_t)co * CIN + ci) * 9 + ky * 3 + kx];
        BT[(size_t)n * K + k] = __float2half(v);
    }
}

// conv1d weights: BT[co][t*CD+ci] = w[co][ci][t]
__global__ void tw1d_kernel(const float* __restrict__ w) {
    int co = blockIdx.x;
    for (int k = threadIdx.x; k < K1D; k += blockDim.x) {
        int t = k / CD, ci = k % CD;
        g_BT1d[(size_t)co * K1D + k] = __float2half(w[((size_t)co * CD + ci) * 3 + t]);
    }
}

// fc1 weights: BT[n][k] = w[k][n]
__global__ void twfc1_kernel(const float* __restrict__ w) {
    int n = blockIdx.x;
    for (int k = threadIdx.x; k < CD; k += blockDim.x)
        g_BTf1[(size_t)n * CD + k] = __float2half(w[(size_t)k * FC1DIM + n]);
}

// ---------------- roi align -> fp16 A of conv1 ----------------
__global__ void roialign_kernel(const float* __restrict__ boxes) {
    __shared__ float swy[6], swx[6];
    __shared__ int sy0[6], sy1[6], sx0[6], sx1[6];
    int s = blockIdx.x;
    if (threadIdx.x == 0) {
        float x1, y1, x2, y2;
        if (s < BB) { x1 = 0.f; y1 = 0.f; x2 = (float)FF; y2 = (float)FF; }
        else {
            const float* bx = boxes + (size_t)(s - BB) * 4;
            x1 = bx[0]; y1 = bx[1]; x2 = bx[2]; y2 = bx[3];
        }
        float rw = fmaxf(x2 - x1, 1.f), rh = fmaxf(y2 - y1, 1.f);
        float scy = rh / 3.0f, scx = rw / 3.0f;
        for (int i = 0; i < 6; i++) {
            float pos = ((float)i + 0.5f) * 0.5f;
            float ys = fminf(fmaxf(y1 + pos * scy, 0.f), 13.f);
            float xs = fminf(fmaxf(x1 + pos * scx, 0.f), 13.f);
            float y0 = floorf(ys), x0 = floorf(xs);
            int y0i = (int)y0, x0i = (int)x0;
            sy0[i] = y0i; sx0[i] = x0i;
            sy1[i] = min(y0i + 1, 13); sx1[i] = min(x0i + 1, 13);
            swy[i] = ys - y0; swx[i] = xs - x0;
        }
    }
    __syncthreads();
    int b = (s < BB) ? s : (s - BB) / NN;
    const float* fm = g_fmapT + (size_t)b * SPAT * CC;
    for (int c = threadIdx.x; c < CC; c += blockDim.x) {
        float acc[9];
        #pragma unroll
        for (int k = 0; k < 9; k++) acc[k] = 0.f;
        #pragma unroll
        for (int sy = 0; sy < 6; sy++) {
            float wy = swy[sy];
            int y0 = sy0[sy], y1 = sy1[sy];
            #pragma unroll
            for (int sx = 0; sx < 6; sx++) {
                float wx = swx[sx];
                int x0 = sx0[sx], x1 = sx1[sx];
                float v00 = fm[(y0 * FF + x0) * CC + c];
                float v01 = fm[(y0 * FF + x1) * CC + c];
                float v10 = fm[(y1 * FF + x0) * CC + c];
                float v11 = fm[(y1 * FF + x1) * CC + c];
                float v = v00 * (1.f - wy) * (1.f - wx) + v01 * (1.f - wy) * wx
                        + v10 * wy * (1.f - wx) + v11 * wy * wx;
                acc[(sy >> 1) * 3 + (sx >> 1)] += v;
            }
        }
        #pragma unroll
        for (int k = 0; k < 9; k++)
            g_roiH[((size_t)s * 9 + k) * CC + c] = __float2half(acc[k] * 0.25f);
    }
}

// ---------------- fp16 tensor-core GEMM ----------------
// C[M][N] = A[M][K] * BT[N][K]^T ; A,BT fp16 row-major; fp32 accumulate.
// CTA tile 128x128, K tile 32, 256 threads, double-buffered cp.async.
#define MODE_CONV      0   // v*scale[c&comask]+shift[..], leaky 0.1
#define MODE_BIAS      1   // v + shift[c]
#define MODE_BIAS_RELU 2   // relu(v + shift[c])

__device__ __forceinline__ void cpasync16(uint32_t dst, const void* src) {
    asm volatile("cp.async.cg.shared.global [%0], [%1], 16;\n" :: "r"(dst), "l"(src));
}

template<int MODE>
__global__ void __launch_bounds__(256) gemm_f16(
    const __half* __restrict__ A, const __half* __restrict__ BT,
    __half* __restrict__ Cout, int M, int N, int K,
    const float* __restrict__ scale, const float* __restrict__ shift,
    int comask, const int* __restrict__ rowmap)
{
    __shared__ __half As[2][128][40];
    __shared__ __half Bs[2][128][40];
    const int tid = threadIdx.x, lane = tid & 31, wid = tid >> 5;
    const int wm = wid >> 2, wn = wid & 3;           // warp grid 2 x 4
    const int m0 = blockIdx.y * 128, n0 = blockIdx.x * 128;

    // staging assignment: each thread loads 2x16B for A and 2x16B for B per tile
    const __half* srcA[2];
    const __half* srcB[2];
    uint32_t sA[2][2], sB[2][2];
    #pragma unroll
    for (int r = 0; r < 2; r++) {
        int i = tid + r * 256;
        int row = i >> 2, seg = i & 3;
        int gr = m0 + row;
        if (rowmap) gr = rowmap[gr];
        srcA[r] = A + (size_t)gr * K + seg * 8;
        srcB[r] = BT + (size_t)(n0 + row) * K + seg * 8;
        #pragma unroll
        for (int b = 0; b < 2; b++) {
            sA[b][r] = (uint32_t)__cvta_generic_to_shared(&As[b][row][seg * 8]);
            sB[b][r] = (uint32_t)__cvta_generic_to_shared(&Bs[b][row][seg * 8]);
        }
    }

    float acc[4][4][4];
    #pragma unroll
    for (int mt = 0; mt < 4; mt++)
        #pragma unroll
        for (int nt = 0; nt < 4; nt++)
            #pragma unroll
            for (int i = 0; i < 4; i++) acc[mt][nt][i] = 0.f;

    const int KT = K >> 5;

    auto stage = [&](int kt, int buf) {
        int k0 = kt << 5;
        #pragma unroll
        for (int r = 0; r < 2; r++) {
            cpasync16(sA[buf][r], srcA[r] + k0);
            cpasync16(sB[buf][r], srcB[r] + k0);
        }
        asm volatile("cp.async.commit_group;\n");
    };

    stage(0, 0);
    for (int kt = 0; kt < KT; kt++) {
        asm volatile("cp.async.wait_group 0;\n");
        __syncthreads();
        if (kt + 1 < KT) stage(kt + 1, (kt + 1) & 1);
        int buf = kt & 1;
        #pragma unroll
        for (int ks = 0; ks < 2; ks++) {
            uint32_t a[4][4], b[4][2];
            int arow = wm * 64 + (lane & 15);
            int acol = ks * 16 + (lane >> 4) * 8;
            #pragma unroll
            for (int mt = 0; mt < 4; mt++) {
                uint32_t addr = (uint32_t)__cvta_generic_to_shared(&As[buf][arow + mt * 16][acol]);
                asm volatile("ldmatrix.sync.aligned.m8n8.x4.shared.b16 {%0,%1,%2,%3},[%4];"
                    : "=r"(a[mt][0]), "=r"(a[mt][1]), "=r"(a[mt][2]), "=r"(a[mt][3]) : "r"(addr));
            }
            int l = lane & 15;
            int brow = wn * 32 + (l & 7);
            int bcol = ks * 16 + (l >> 3) * 8;
            #pragma unroll
            for (int nt = 0; nt < 4; nt++) {
                uint32_t addr = (uint32_t)__cvta_generic_to_shared(&Bs[buf][brow + nt * 8][bcol]);
                asm volatile("ldmatrix.sync.aligned.m8n8.x2.shared.b16 {%0,%1},[%2];"
                    : "=r"(b[nt][0]), "=r"(b[nt][1]) : "r"(addr));
            }
            #pragma unroll
            for (int mt = 0; mt < 4; mt++)
                #pragma unroll
                for (int nt = 0; nt < 4; nt++)
                    asm volatile("mma.sync.aligned.m16n8k16.row.col.f32.f16.f16.f32 "
                        "{%0,%1,%2,%3},{%4,%5,%6,%7},{%8,%9},{%0,%1,%2,%3};"
                        : "+f"(acc[mt][nt][0]), "+f"(acc[mt][nt][1]),
                          "+f"(acc[mt][nt][2]), "+f"(acc[mt][nt][3])
                        : "r"(a[mt][0]), "r"(a[mt][1]), "r"(a[mt][2]), "r"(a[mt][3]),
                          "r"(b[nt][0]), "r"(b[nt][1]));
        }
    }

    // epilogue
    #pragma unroll
    for (int mt = 0; mt < 4; mt++) {
        int r0 = m0 + wm * 64 + mt * 16 + (lane >> 2);
        #pragma unroll
        for (int nt = 0; nt < 4; nt++) {
            int c0 = n0 + wn * 32 + nt * 8 + (lane & 3) * 2;
            #pragma unroll
            for (int hh = 0; hh < 2; hh++) {
                int rr = r0 + hh * 8;
                float v0 = acc[mt][nt][hh * 2 + 0];
                float v1 = acc[mt][nt][hh * 2 + 1];
                if (MODE == MODE_CONV) {
                    int co0 = c0 & comask, co1 = (c0 + 1) & comask;
                    v0 = v0 * scale[co0] + shift[co0];
                    v1 = v1 * scale[co1] + shift[co1];
                    v0 = v0 > 0.f ? v0 : 0.1f * v0;
                    v1 = v1 > 0.f ? v1 : 0.1f * v1;
                } else {
                    v0 += shift[c0];
                    v1 += shift[c0 + 1];
                    if (MODE == MODE_BIAS_RELU) { v0 = fmaxf(v0, 0.f); v1 = fmaxf(v1, 0.f); }
                }
                *(__half2*)(Cout + (size_t)rr * N + c0) = __floats2half2_rn(v0, v1);
            }
        }
    }
}

// ---------------- scatter-add + im2col for conv1d ----------------
// behavior channel c (=co*9+k) maps to gemm-output column (c%9)*C2 + c/9
__global__ void buildbehavior_kernel(const int* __restrict__ person_idx) {
    int p = blockIdx.x / BB, b = blockIdx.x % BB;
    __shared__ int pid[NN];
    if (threadIdx.x < NN) pid[threadIdx.x] = person_idx[b * NN + threadIdx.x];
    __syncthreads();
    const __half* rowG = g_out2h + (size_t)b * N2;
    size_t base = (size_t)(p * BB + b) * K1D;
    for (int c = threadIdx.x; c < CD; c += blockDim.x) {
        int col = (c % 9) * C2 + (c / 9);
        float v = __half2float(rowG[col]);
        #pragma unroll
        for (int n = 0; n < NN; n++)
            if (pid[n] == p)
                v += __half2float(g_out2h[(size_t)(BB + b * NN + n) * N2 + col]);
        __half hv = __float2half(v);
        if (b + 1 < BB) g_A1d[(size_t)(p * BB + b + 1) * K1D + c] = hv;   // t=0
        g_A1d[base + CD + c] = hv;                                        // t=1
        if (b > 0) g_A1d[(size_t)(p * BB + b - 1) * K1D + 2 * CD + c] = hv; // t=2
        if (b == 0)      g_A1d[base + c] = __float2half(0.f);
        if (b == BB - 1) g_A1d[base + 2 * CD + c] = __float2half(0.f);
    }
}

// ---------------- rowmap: feats row r -> x1d row p*64+b ----------------
__global__ void rowmap_kernel(const int* __restrict__ person_idx) {
    int r = blockIdx.x * blockDim.x + threadIdx.x;
    if (r < BB * NN) {
        int b = r >> 4;
        g_rowmap[r] = person_idx[r] * BB + b;
    }
}

// ---------------- fc2 ----------------
__global__ void fc2_kernel(const float* __restrict__ w, const float* __restrict__ bias,
                           float* __restrict__ out) {
    __shared__ float red[4][32];
    int r = blockIdx.x;
    int t = threadIdx.x;
    int n = t & 31, kg = t >> 5;         // 4 k-groups of 256
    float acc = 0.f;
    if (n < NBCLS) {
        const __half* hr = g_hh + (size_t)r * FC1DIM + kg * 256;
        for (int j = 0; j < 256; j++)
            acc = fmaf(__half2float(hr[j]), w[(size_t)(kg * 256 + j) * NBCLS + n], acc);
    }
    red[kg][n] = acc;
    __syncthreads();
    if (kg == 0 && n < NBCLS)
        out[(size_t)r * NBCLS + n] = red[0][n] + red[1][n] + red[2][n] + red[3][n] + bias[n];
}

// ---------------- launch ----------------
extern "C" void kernel_launch(void* const* d_in, const int* in_sizes, int n_in,
                              void* d_out, int out_size) {
    const float* fmap      = (const float*)d_in[0];
    const float* boxes     = (const float*)d_in[1];
    const int*   person_idx= (const int*)  d_in[2];
    const float* conv1_w   = (const float*)d_in[3];
    const float* bn1_g     = (const float*)d_in[4];
    const float* bn1_b     = (const float*)d_in[5];
    const float* bn1_m     = (const float*)d_in[6];
    const float* bn1_v     = (const float*)d_in[7];
    const float* conv2_w   = (const float*)d_in[8];
    const float* bn2_g     = (const float*)d_in[9];
    const float* bn2_b     = (const float*)d_in[10];
    const float* bn2_m     = (const float*)d_in[11];
    const float* bn2_v     = (const float*)d_in[12];
    const float* conv1d_w  = (const float*)d_in[13];
    const float* conv1d_b  = (const float*)d_in[14];
    const float* fc1_w     = (const float*)d_in[15];
    const float* fc1_b     = (const float*)d_in[16];
    const float* fc2_w     = (const float*)d_in[17];
    const float* fc2_b     = (const float*)d_in[18];
    float* out = (float*)d_out;

    void *p_roiH, *p_BT1, *p_out1, *p_BT2, *p_out2, *p_A1d, *p_BT1d, *p_x1d,
         *p_BTf1, *p_hh, *p_sc1, *p_sh1, *p_sc2, *p_sh2, *p_rowmap;
    cudaGetSymbolAddress(&p_roiH, g_roiH);
    cudaGetSymbolAddress(&p_BT1,  g_BT1);
    cudaGetSymbolAddress(&p_out1, g_out1h);
    cudaGetSymbolAddress(&p_BT2,  g_BT2);
    cudaGetSymbolAddress(&p_out2, g_out2h);
    cudaGetSymbolAddress(&p_A1d,  g_A1d);
    cudaGetSymbolAddress(&p_BT1d, g_BT1d);
    cudaGetSymbolAddress(&p_x1d,  g_x1dh);
    cudaGetSymbolAddress(&p_BTf1, g_BTf1);
    cudaGetSymbolAddress(&p_hh,   g_hh);
    cudaGetSymbolAddress(&p_sc1,  g_scale1);
    cudaGetSymbolAddress(&p_sh1,  g_shift1);
    cudaGetSymbolAddress(&p_sc2,  g_scale2);
    cudaGetSymbolAddress(&p_sh2,  g_shift2);
    cudaGetSymbolAddress(&p_rowmap, g_rowmap);

    // ---- prep ----
    bnfold_kernel<<<3, 256>>>(bn1_g, bn1_b, bn1_m, bn1_v, bn2_g, bn2_b, bn2_m, bn2_v);
    tfmap_kernel<<<BB * SPAT, 256>>>(fmap);
    expand_conv_w<<<N1, 256>>>(conv1_w, (__half*)p_BT1, CC, C1);
    expand_conv_w<<<N2, 256>>>(conv2_w, (__half*)p_BT2, C1, C2);
    tw1d_kernel<<<CD, 256>>>(conv1d_w);
    twfc1_kernel<<<FC1DIM, 256>>>(fc1_w);
    rowmap_kernel<<<4, 256>>>(person_idx);

    // ---- roi align ----
    roialign_kernel<<<S_TOT, 256>>>(boxes);

    // ---- conv1 (M=1152, N=4608, K=9216) ----
    gemm_f16<MODE_CONV><<<dim3(N1 / 128, S_PAD / 128), 256>>>(
        (const __half*)p_roiH, (const __half*)p_BT1, (__half*)p_out1,
        S_PAD, N1, K1, (const float*)p_sc1, (const float*)p_sh1, C1 - 1, nullptr);

    // ---- conv2 (M=1152, N=2304, K=4608) ----
    gemm_f16<MODE_CONV><<<dim3(N2 / 128, S_PAD / 128), 256>>>(
        (const __half*)p_out1, (const __half*)p_BT2, (__half*)p_out2,
        S_PAD, N2, K2, (const float*)p_sc2, (const float*)p_sh2, C2 - 1, nullptr);

    // ---- scatter-add + im2col ----
    buildbehavior_kernel<<<PP * BB, 256>>>(person_idx);

    // ---- conv1d (M=1280, N=2304, K=6912) ----
    gemm_f16<MODE_BIAS><<<dim3(CD / 128, M1D / 128), 256>>>(
        (const __half*)p_A1d, (const __half*)p_BT1d, (__half*)p_x1d,
        M1D, CD, K1D, nullptr, conv1d_b, 0, nullptr);

    // ---- fc1 (M=1024, N=1024, K=2304) with gathered rows ----
    gemm_f16<MODE_BIAS_RELU><<<dim3(FC1DIM / 128, (BB * NN) / 128), 256>>>(
        (const __half*)p_x1d, (const __half*)p_BTf1, (__half*)p_hh,
        BB * NN, FC1DIM, CD, nullptr, fc1_b, 0, (const int*)p_rowmap);

    // ---- fc2 -> output ----
    fc2_kernel<<<BB * NN, 128>>>(fc2_w, fc2_b, out);
}

// round 7
// speedup vs baseline: 5.1566x; 1.0594x over previous
#include <cuda_runtime.h>
#include <cuda_fp16.h>
#include <cstdint>

// ---------------- problem constants ----------------
#define BB 64
#define NN 16
#define PP 20
#define NBCLS 30
#define CC 1024
#define FF 14
#define SPAT 196
#define S_TOT 1088
#define S_PAD 1152
#define C1 512
#define C2 256
#define CD 2304
#define K1 (9*CC)           // 9216
#define N1 (9*C1)           // 4608
#define K2 (9*C1)           // 4608
#define N2 (9*C2)           // 2304
#define K1D (3*CD)          // 6912
#define M1D (PP*BB)         // 1280
#define FC1DIM 1024

// ---------------- static device scratch ----------------
__device__ float  g_fmapT[BB*SPAT*CC];
__device__ __half g_roiH[(size_t)S_PAD*K1];
__device__ __half g_BT1[(size_t)N1*K1];
__device__ __half g_out1h[(size_t)S_PAD*N1];
__device__ __half g_BT2[(size_t)N2*K2];
__device__ __half g_out2h[(size_t)S_PAD*N2];
__device__ __half g_A1d[(size_t)M1D*K1D];
__device__ __half g_BT1d[(size_t)CD*K1D];
__device__ __half g_x1dh[(size_t)M1D*CD];
__device__ __half g_feats[(size_t)BB*NN*CD];
__device__ __half g_BTf1[(size_t)FC1DIM*CD];
__device__ __half g_hh[(size_t)BB*NN*FC1DIM];
__device__ float  g_scale1[C1], g_shift1[C1];
__device__ float  g_scale2[C2], g_shift2[C2];

// ---------------- BN folding ----------------
__global__ void bnfold_kernel(const float* g1, const float* b1, const float* m1, const float* v1,
                              const float* g2, const float* b2, const float* m2, const float* v2) {
    int t = blockIdx.x * blockDim.x + threadIdx.x;
    if (t < C1) {
        float s = g1[t] * rsqrtf(v1[t] + 1e-5f);
        g_scale1[t] = s;
        g_shift1[t] = b1[t] - m1[t] * s;
    } else if (t < C1 + C2) {
        int i = t - C1;
        float s = g2[i] * rsqrtf(v2[i] + 1e-5f);
        g_scale2[i] = s;
        g_shift2[i] = b2[i] - m2[i] * s;
    }
}

// ---------------- tiled fmap transpose [b][c][yx] -> [b][yx][c] ----------------
__global__ void tfmap_kernel(const float* __restrict__ fmap) {
    __shared__ float t[32][33];
    int b = blockIdx.z;
    int c0 = blockIdx.y * 32, yx0 = blockIdx.x * 32;
    int tx = threadIdx.x, ty = threadIdx.y;
    #pragma unroll
    for (int i = ty; i < 32; i += 8) {
        int yx = yx0 + tx;
        t[i][tx] = (yx < SPAT) ? fmap[((size_t)b * CC + c0 + i) * SPAT + yx] : 0.f;
    }
    __syncthreads();
    #pragma unroll
    for (int i = ty; i < 32; i += 8) {
        int yx = yx0 + i;
        if (yx < SPAT)
            g_fmapT[((size_t)b * SPAT + yx) * CC + c0 + tx] = t[tx][i];
    }
}

// ---------------- expanded conv weights: BT[n][k], n=ko*COUT+co, k=ki*CIN+ci ----------------
template<int CIN, int COUT>
__global__ void expand_conv_w(const float* __restrict__ w, __half* __restrict__ BT) {
    int n = blockIdx.x;
    int co = n & (COUT - 1), ko = n / COUT;
    int oy = ko / 3, ox = ko % 3;
    const int K = 9 * CIN;
    for (int k = threadIdx.x; k < K; k += blockDim.x) {
        int ki = k / CIN, ci = k & (CIN - 1);
        int ky = ki / 3 - oy + 1, kx = ki % 3 - ox + 1;
        float v = 0.f;
        if ((unsigned)ky < 3u && (unsigned)kx < 3u)
            v = w[((size_t)co * CIN + ci) * 9 + ky * 3 + kx];
        BT[(size_t)n * K + k] = __float2half(v);
    }
}

// conv1d weights: BT[co][t*CD+ci] = w[co][ci][t]
__global__ void tw1d_kernel(const float* __restrict__ w) {
    int co = blockIdx.x;
    for (int ci = threadIdx.x; ci < CD; ci += blockDim.x) {
        #pragma unroll
        for (int t = 0; t < 3; t++)
            g_BT1d[(size_t)co * K1D + t * CD + ci] = __float2half(w[((size_t)co * CD + ci) * 3 + t]);
    }
}

// fc1 weights: BT[n][k] = w[k][n]
__global__ void twfc1_kernel(const float* __restrict__ w) {
    int n = blockIdx.x;
    for (int k = threadIdx.x; k < CD; k += blockDim.x)
        g_BTf1[(size_t)n * CD + k] = __float2half(w[(size_t)k * FC1DIM + n]);
}

// ---------------- roi align -> fp16 A of conv1 ----------------
__global__ void roialign_kernel(const float* __restrict__ boxes) {
    __shared__ float swy[6], swx[6];
    __shared__ int sy0[6], sy1[6], sx0[6], sx1[6];
    int s = blockIdx.x;
    if (threadIdx.x == 0) {
        float x1, y1, x2, y2;
        if (s < BB) { x1 = 0.f; y1 = 0.f; x2 = (float)FF; y2 = (float)FF; }
        else {
            const float* bx = boxes + (size_t)(s - BB) * 4;
            x1 = bx[0]; y1 = bx[1]; x2 = bx[2]; y2 = bx[3];
        }
        float rw = fmaxf(x2 - x1, 1.f), rh = fmaxf(y2 - y1, 1.f);
        float scy = rh / 3.0f, scx = rw / 3.0f;
        for (int i = 0; i < 6; i++) {
            float pos = ((float)i + 0.5f) * 0.5f;
            float ys = fminf(fmaxf(y1 + pos * scy, 0.f), 13.f);
            float xs = fminf(fmaxf(x1 + pos * scx, 0.f), 13.f);
            float y0 = floorf(ys), x0 = floorf(xs);
            int y0i = (int)y0, x0i = (int)x0;
            sy0[i] = y0i; sx0[i] = x0i;
            sy1[i] = min(y0i + 1, 13); sx1[i] = min(x0i + 1, 13);
            swy[i] = ys - y0; swx[i] = xs - x0;
        }
    }
    __syncthreads();
    int b = (s < BB) ? s : (s - BB) / NN;
    const float* fm = g_fmapT + (size_t)b * SPAT * CC;
    for (int c = threadIdx.x; c < CC; c += blockDim.x) {
        float acc[9];
        #pragma unroll
        for (int k = 0; k < 9; k++) acc[k] = 0.f;
        #pragma unroll
        for (int sy = 0; sy < 6; sy++) {
            float wy = swy[sy];
            int y0 = sy0[sy], y1 = sy1[sy];
            #pragma unroll
            for (int sx = 0; sx < 6; sx++) {
                float wx = swx[sx];
                int x0 = sx0[sx], x1 = sx1[sx];
                float v00 = fm[(y0 * FF + x0) * CC + c];
                float v01 = fm[(y0 * FF + x1) * CC + c];
                float v10 = fm[(y1 * FF + x0) * CC + c];
                float v11 = fm[(y1 * FF + x1) * CC + c];
                float v = v00 * (1.f - wy) * (1.f - wx) + v01 * (1.f - wy) * wx
                        + v10 * wy * (1.f - wx) + v11 * wy * wx;
                acc[(sy >> 1) * 3 + (sx >> 1)] += v;
            }
        }
        #pragma unroll
        for (int k = 0; k < 9; k++)
            g_roiH[((size_t)s * 9 + k) * CC + c] = __float2half(acc[k] * 0.25f);
    }
}

// ---------------- fp16 tensor-core GEMM (mma.sync), 4-stage pipeline ----------------
// C[M][N] = A[M][K] * BT[N][K]^T ; fp16 in, fp32 accumulate.
// CTA tile 128x128, K tile 32, 256 threads, 4-stage cp.async, wait_group 2.
#define MODE_CONV      0   // v*scale[c&comask]+shift[..], leaky 0.1
#define MODE_BIAS      1   // v + shift[c]
#define MODE_BIAS_RELU 2   // relu(v + shift[c])

#define STAGE_BYTES 10240          // 128 rows x 40 halves x 2B
#define SMEM_A_OFF  0
#define SMEM_B_OFF  (4 * STAGE_BYTES)
#define SMEM_TOTAL  (8 * STAGE_BYTES)   // 81920

__device__ __forceinline__ void cpasync16(uint32_t dst, const void* src) {
    asm volatile("cp.async.cg.shared.global [%0], [%1], 16;\n" :: "r"(dst), "l"(src));
}

template<int MODE>
__global__ void __launch_bounds__(256) gemm_f16(
    const __half* __restrict__ A, const __half* __restrict__ BT,
    __half* __restrict__ Cout, int N_, int K,
    const float* __restrict__ scale, const float* __restrict__ shift, int comask)
{
    extern __shared__ char smem[];
    uint32_t sbase;
    asm("{ .reg .u64 t; cvta.to.shared.u64 t, %1; cvt.u32.u64 %0, t; }" : "=r"(sbase) : "l"(smem));
    const int tid = threadIdx.x, lane = tid & 31, wid = tid >> 5;
    const int wm = wid >> 2, wn = wid & 3;           // warp grid 2 x 4
    const int m0 = blockIdx.y * 128, n0 = blockIdx.x * 128;

    // per-thread staging: 2 x 16B for A, 2 x 16B for B per stage
    const __half* srcA[2];
    const __half* srcB[2];
    uint32_t dstA[2], dstB[2];
    #pragma unroll
    for (int r = 0; r < 2; r++) {
        int q = tid + r * 256;                 // 0..511
        int row = q >> 2, seg = q & 3;
        srcA[r] = A + (size_t)(m0 + row) * K + seg * 8;
        srcB[r] = BT + (size_t)(n0 + row) * K + seg * 8;
        dstA[r] = sbase + SMEM_A_OFF + row * 80 + seg * 16;
        dstB[r] = sbase + SMEM_B_OFF + row * 80 + seg * 16;
    }

    float acc[4][4][4];
    #pragma unroll
    for (int mt = 0; mt < 4; mt++)
        #pragma unroll
        for (int nt = 0; nt < 4; nt++)
            #pragma unroll
            for (int i = 0; i < 4; i++) acc[mt][nt][i] = 0.f;

    const int KT = K >> 5;

    auto stage = [&](int s) {
        int slot = s & 3;
        int k0 = s << 5;
        #pragma unroll
        for (int r = 0; r < 2; r++) {
            cpasync16(dstA[r] + slot * STAGE_BYTES, srcA[r] + k0);
            cpasync16(dstB[r] + slot * STAGE_BYTES, srcB[r] + k0);
        }
        asm volatile("cp.async.commit_group;\n");
    };

    stage(0); stage(1); stage(2);

    // fragment base addresses (byte offsets inside one stage)
    const int arow = wm * 64 + (lane & 15);
    uint32_t aAddrBase = sbase + SMEM_A_OFF + arow * 80 + (lane >> 4) * 16;
    const int brow = wn * 32 + ((lane >> 3) & 1) * 8 + (lane & 7);
    uint32_t bAddrBase = sbase + SMEM_B_OFF + brow * 80 + (lane >> 4) * 16;

    for (int c = 0; c < KT; c++) {
        asm volatile("cp.async.wait_group 2;\n");
        __syncthreads();
        if (c + 3 < KT) stage(c + 3);
        int slot = c & 3;
        uint32_t aS = aAddrBase + slot * STAGE_BYTES;
        uint32_t bS = bAddrBase + slot * STAGE_BYTES;
        #pragma unroll
        for (int ks = 0; ks < 2; ks++) {
            uint32_t a[4][4], b[4][2];
            #pragma unroll
            for (int mt = 0; mt < 4; mt++) {
                asm volatile("ldmatrix.sync.aligned.m8n8.x4.shared.b16 {%0,%1,%2,%3},[%4];"
                    : "=r"(a[mt][0]), "=r"(a[mt][1]), "=r"(a[mt][2]), "=r"(a[mt][3])
                    : "r"(aS + mt * 16 * 80 + ks * 32));
            }
            #pragma unroll
            for (int nt2 = 0; nt2 < 2; nt2++) {
                uint32_t r0, r1, r2, r3;
                asm volatile("ldmatrix.sync.aligned.m8n8.x4.shared.b16 {%0,%1,%2,%3},[%4];"
                    : "=r"(r0), "=r"(r1), "=r"(r2), "=r"(r3)
                    : "r"(bS + nt2 * 16 * 80 + ks * 32));
                b[nt2 * 2 + 0][0] = r0; b[nt2 * 2 + 0][1] = r2;
                b[nt2 * 2 + 1][0] = r1; b[nt2 * 2 + 1][1] = r3;
            }
            #pragma unroll
            for (int mt = 0; mt < 4; mt++)
                #pragma unroll
                for (int nt = 0; nt < 4; nt++)
                    asm volatile("mma.sync.aligned.m16n8k16.row.col.f32.f16.f16.f32 "
                        "{%0,%1,%2,%3},{%4,%5,%6,%7},{%8,%9},{%0,%1,%2,%3};"
                        : "+f"(acc[mt][nt][0]), "+f"(acc[mt][nt][1]),
                          "+f"(acc[mt][nt][2]), "+f"(acc[mt][nt][3])
                        : "r"(a[mt][0]), "r"(a[mt][1]), "r"(a[mt][2]), "r"(a[mt][3]),
                          "r"(b[nt][0]), "r"(b[nt][1]));
        }
    }

    // epilogue: direct gmem stores
    #pragma unroll
    for (int mt = 0; mt < 4; mt++) {
        int r0 = m0 + wm * 64 + mt * 16 + (lane >> 2);
        #pragma unroll
        for (int nt = 0; nt < 4; nt++) {
            int c0 = n0 + wn * 32 + nt * 8 + (lane & 3) * 2;
            #pragma unroll
            for (int hh = 0; hh < 2; hh++) {
                int rr = r0 + hh * 8;
                float v0 = acc[mt][nt][hh * 2 + 0];
                float v1 = acc[mt][nt][hh * 2 + 1];
                if (MODE == MODE_CONV) {
                    int c0i = c0 & comask, c1i = (c0 + 1) & comask;
                    v0 = v0 * scale[c0i] + shift[c0i];
                    v1 = v1 * scale[c1i] + shift[c1i];
                    v0 = v0 > 0.f ? v0 : 0.1f * v0;
                    v1 = v1 > 0.f ? v1 : 0.1f * v1;
                } else {
                    v0 += shift[c0];
                    v1 += shift[c0 + 1];
                    if (MODE == MODE_BIAS_RELU) { v0 = fmaxf(v0, 0.f); v1 = fmaxf(v1, 0.f); }
                }
                *(__half2*)(Cout + (size_t)rr * N_ + c0) = __floats2half2_rn(v0, v1);
            }
        }
    }
}

// ---------------- scatter-add + im2col for conv1d ----------------
__global__ void buildbehavior_kernel(const int* __restrict__ person_idx) {
    int p = blockIdx.x / BB, b = blockIdx.x % BB;
    __shared__ int pid[NN];
    if (threadIdx.x < NN) pid[threadIdx.x] = person_idx[b * NN + threadIdx.x];
    __syncthreads();
    const __half* rowG = g_out2h + (size_t)b * N2;
    size_t base = (size_t)(p * BB + b) * K1D;
    for (int c = threadIdx.x; c < CD; c += blockDim.x) {
        int col = (c % 9) * C2 + (c / 9);
        float v = __half2float(rowG[col]);
        #pragma unroll
        for (int n = 0; n < NN; n++)
            if (pid[n] == p)
                v += __half2float(g_out2h[(size_t)(BB + b * NN + n) * N2 + col]);
        __half hv = __float2half(v);
        if (b + 1 < BB) g_A1d[(size_t)(p * BB + b + 1) * K1D + c] = hv;     // t=0
        g_A1d[base + CD + c] = hv;                                          // t=1
        if (b > 0) g_A1d[(size_t)(p * BB + b - 1) * K1D + 2 * CD + c] = hv; // t=2
        if (b == 0)      g_A1d[base + c] = __float2half(0.f);
        if (b == BB - 1) g_A1d[base + 2 * CD + c] = __float2half(0.f);
    }
}

// ---------------- pre-gather rows for fc1 ----------------
__global__ void gatherfeats_kernel(const int* __restrict__ person_idx) {
    int r = blockIdx.x;
    int b = r >> 4;
    int p = person_idx[r];
    const float4* src = (const float4*)(g_x1dh + (size_t)(p * BB + b) * CD);
    float4* dst = (float4*)(g_feats + (size_t)r * CD);
    for (int c = threadIdx.x; c < CD / 8; c += blockDim.x)
        dst[c] = src[c];
}

// ---------------- fc2 ----------------
__global__ void fc2_kernel(const float* __restrict__ w, const float* __restrict__ bias,
                           float* __restrict__ out) {
    __shared__ float red[4][32];
    int r = blockIdx.x;
    int t = threadIdx.x;
    int n = t & 31, kg = t >> 5;
    float acc = 0.f;
    if (n < NBCLS) {
        const __half* hr = g_hh + (size_t)r * FC1DIM + kg * 256;
        for (int j = 0; j < 256; j++)
            acc = fmaf(__half2float(hr[j]), w[(size_t)(kg * 256 + j) * NBCLS + n], acc);
    }
    red[kg][n] = acc;
    __syncthreads();
    if (kg == 0 && n < NBCLS)
        out[(size_t)r * NBCLS + n] = red[0][n] + red[1][n] + red[2][n] + red[3][n] + bias[n];
}

// ---------------- launch ----------------
extern "C" void kernel_launch(void* const* d_in, const int* in_sizes, int n_in,
                              void* d_out, int out_size) {
    const float* fmap      = (const float*)d_in[0];
    const float* boxes     = (const float*)d_in[1];
    const int*   person_idx= (const int*)  d_in[2];
    const float* conv1_w   = (const float*)d_in[3];
    const float* bn1_g     = (const float*)d_in[4];
    const float* bn1_b     = (const float*)d_in[5];
    const float* bn1_m     = (const float*)d_in[6];
    const float* bn1_v     = (const float*)d_in[7];
    const float* conv2_w   = (const float*)d_in[8];
    const float* bn2_g     = (const float*)d_in[9];
    const float* bn2_b     = (const float*)d_in[10];
    const float* bn2_m     = (const float*)d_in[11];
    const float* bn2_v     = (const float*)d_in[12];
    const float* conv1d_w  = (const float*)d_in[13];
    const float* conv1d_b  = (const float*)d_in[14];
    const float* fc1_w     = (const float*)d_in[15];
    const float* fc1_b     = (const float*)d_in[16];
    const float* fc2_w     = (const float*)d_in[17];
    const float* fc2_b     = (const float*)d_in[18];
    float* out = (float*)d_out;

    void *p_roiH, *p_BT1, *p_out1, *p_BT2, *p_out2, *p_A1d, *p_BT1d, *p_x1d,
         *p_feats, *p_BTf1, *p_hh, *p_sc1, *p_sh1, *p_sc2, *p_sh2;
    cudaGetSymbolAddress(&p_roiH, g_roiH);
    cudaGetSymbolAddress(&p_BT1,  g_BT1);
    cudaGetSymbolAddress(&p_out1, g_out1h);
    cudaGetSymbolAddress(&p_BT2,  g_BT2);
    cudaGetSymbolAddress(&p_out2, g_out2h);
    cudaGetSymbolAddress(&p_A1d,  g_A1d);
    cudaGetSymbolAddress(&p_BT1d, g_BT1d);
    cudaGetSymbolAddress(&p_x1d,  g_x1dh);
    cudaGetSymbolAddress(&p_feats, g_feats);
    cudaGetSymbolAddress(&p_BTf1, g_BTf1);
    cudaGetSymbolAddress(&p_hh,   g_hh);
    cudaGetSymbolAddress(&p_sc1,  g_scale1);
    cudaGetSymbolAddress(&p_sh1,  g_shift1);
    cudaGetSymbolAddress(&p_sc2,  g_scale2);
    cudaGetSymbolAddress(&p_sh2,  g_shift2);

    cudaFuncSetAttribute(gemm_f16<MODE_CONV>,
                         cudaFuncAttributeMaxDynamicSharedMemorySize, SMEM_TOTAL);
    cudaFuncSetAttribute(gemm_f16<MODE_BIAS>,
                         cudaFuncAttributeMaxDynamicSharedMemorySize, SMEM_TOTAL);
    cudaFuncSetAttribute(gemm_f16<MODE_BIAS_RELU>,
                         cudaFuncAttributeMaxDynamicSharedMemorySize, SMEM_TOTAL);

    // ---- prep ----
    bnfold_kernel<<<3, 256>>>(bn1_g, bn1_b, bn1_m, bn1_v, bn2_g, bn2_b, bn2_m, bn2_v);
    tfmap_kernel<<<dim3(7, 32, 64), dim3(32, 8)>>>(fmap);
    expand_conv_w<CC, C1><<<N1, 256>>>(conv1_w, (__half*)p_BT1);
    expand_conv_w<C1, C2><<<N2, 256>>>(conv2_w, (__half*)p_BT2);
    tw1d_kernel<<<CD, 256>>>(conv1d_w);
    twfc1_kernel<<<FC1DIM, 256>>>(fc1_w);

    // ---- roi align ----
    roialign_kernel<<<S_TOT, 256>>>(boxes);

    // ---- conv1: M=1152, N=4608, K=9216 ----
    gemm_f16<MODE_CONV><<<dim3(N1 / 128, S_PAD / 128), 256, SMEM_TOTAL>>>(
        (const __half*)p_roiH, (const __half*)p_BT1, (__half*)p_out1,
        N1, K1, (const float*)p_sc1, (const float*)p_sh1, C1 - 1);

    // ---- conv2: M=1152, N=2304, K=4608 ----
    gemm_f16<MODE_CONV><<<dim3(N2 / 128, S_PAD / 128), 256, SMEM_TOTAL>>>(
        (const __half*)p_out1, (const __half*)p_BT2, (__half*)p_out2,
        N2, K2, (const float*)p_sc2, (const float*)p_sh2, C2 - 1);

    // ---- scatter-add + im2col ----
    buildbehavior_kernel<<<PP * BB, 256>>>(person_idx);

    // ---- conv1d: M=1280, N=2304, K=6912 ----
    gemm_f16<MODE_BIAS><<<dim3(CD / 128, M1D / 128), 256, SMEM_TOTAL>>>(
        (const __half*)p_A1d, (const __half*)p_BT1d, (__half*)p_x1d,
        CD, K1D, nullptr, conv1d_b, 0);

    // ---- gather person rows ----
    gatherfeats_kernel<<<BB * NN, 256>>>(person_idx);

    // ---- fc1: M=1024, N=1024, K=2304 ----
    gemm_f16<MODE_BIAS_RELU><<<dim3(FC1DIM / 128, (BB * NN) / 128), 256, SMEM_TOTAL>>>(
        (const __half*)p_feats, (const __half*)p_BTf1, (__half*)p_hh,
        FC1DIM, CD, nullptr, fc1_b, 0);

    // ---- fc2 -> output ----
    fc2_kernel<<<BB * NN, 128>>>(fc2_w, fc2_b, out);
}

// round 8
// speedup vs baseline: 5.5848x; 1.0830x over previous
#include <cuda_runtime.h>
#include <cuda_fp16.h>
#include <cstdint>

// ---------------- problem constants ----------------
#define BB 64
#define NN 16
#define PP 20
#define NBCLS 30
#define CC 1024
#define FF 14
#define SPAT 196
#define S_TOT 1088
#define S_PAD 1152
#define C1 512
#define C2 256
#define CD 2304
#define K1 (9*CC)           // 9216
#define N1 (9*C1)           // 4608
#define K2 (9*C1)           // 4608
#define N2 (9*C2)           // 2304
#define K1D (3*CD)          // 6912
#define M1D (PP*BB)         // 1280
#define FC1DIM 1024

// ---------------- static device scratch ----------------
__device__ float  g_fmapT[BB*SPAT*CC];
__device__ __half g_roiH[(size_t)S_PAD*K1];
__device__ __half g_BT1[(size_t)N1*K1];
__device__ __half g_out1h[(size_t)S_PAD*N1];
__device__ __half g_BT2[(size_t)N2*K2];
__device__ __half g_out2h[(size_t)S_PAD*N2];
__device__ __half g_A1d[(size_t)M1D*K1D];
__device__ __half g_BT1d[(size_t)CD*K1D];
__device__ __half g_x1dh[(size_t)M1D*CD];
__device__ __half g_feats[(size_t)BB*NN*CD];
__device__ __half g_BTf1[(size_t)FC1DIM*CD];
__device__ __half g_hh[(size_t)BB*NN*FC1DIM];
__device__ float  g_scale1[C1], g_shift1[C1];
__device__ float  g_scale2[C2], g_shift2[C2];

// ---------------- BN folding ----------------
__global__ void bnfold_kernel(const float* g1, const float* b1, const float* m1, const float* v1,
                              const float* g2, const float* b2, const float* m2, const float* v2) {
    int t = blockIdx.x * blockDim.x + threadIdx.x;
    if (t < C1) {
        float s = g1[t] * rsqrtf(v1[t] + 1e-5f);
        g_scale1[t] = s;
        g_shift1[t] = b1[t] - m1[t] * s;
    } else if (t < C1 + C2) {
        int i = t - C1;
        float s = g2[i] * rsqrtf(v2[i] + 1e-5f);
        g_scale2[i] = s;
        g_shift2[i] = b2[i] - m2[i] * s;
    }
}

// ---------------- tiled fmap transpose [b][c][yx] -> [b][yx][c] ----------------
__global__ void tfmap_kernel(const float* __restrict__ fmap) {
    __shared__ float t[32][33];
    int b = blockIdx.z;
    int c0 = blockIdx.y * 32, yx0 = blockIdx.x * 32;
    int tx = threadIdx.x, ty = threadIdx.y;
    #pragma unroll
    for (int i = ty; i < 32; i += 8) {
        int yx = yx0 + tx;
        t[i][tx] = (yx < SPAT) ? fmap[((size_t)b * CC + c0 + i) * SPAT + yx] : 0.f;
    }
    __syncthreads();
    #pragma unroll
    for (int i = ty; i < 32; i += 8) {
        int yx = yx0 + i;
        if (yx < SPAT)
            g_fmapT[((size_t)b * SPAT + yx) * CC + c0 + tx] = t[tx][i];
    }
}

// ---------------- expanded conv weights: BT[n][k], n=ko*COUT+co, k=ki*CIN+ci ----------------
template<int CIN, int COUT>
__global__ void expand_conv_w(const float* __restrict__ w, __half* __restrict__ BT) {
    int n = blockIdx.x;
    int co = n & (COUT - 1), ko = n / COUT;
    int oy = ko / 3, ox = ko % 3;
    const int K = 9 * CIN;
    for (int k = threadIdx.x; k < K; k += blockDim.x) {
        int ki = k / CIN, ci = k & (CIN - 1);
        int ky = ki / 3 - oy + 1, kx = ki % 3 - ox + 1;
        float v = 0.f;
        if ((unsigned)ky < 3u && (unsigned)kx < 3u)
            v = w[((size_t)co * CIN + ci) * 9 + ky * 3 + kx];
        BT[(size_t)n * K + k] = __float2half(v);
    }
}

// conv1d weights: BT[co][t*CD+ci] = w[co][ci][t]
__global__ void tw1d_kernel(const float* __restrict__ w) {
    int co = blockIdx.x;
    for (int ci = threadIdx.x; ci < CD; ci += blockDim.x) {
        #pragma unroll
        for (int t = 0; t < 3; t++)
            g_BT1d[(size_t)co * K1D + t * CD + ci] = __float2half(w[((size_t)co * CD + ci) * 3 + t]);
    }
}

// fc1 weights: BT[n][k] = w[k][n]
__global__ void twfc1_kernel(const float* __restrict__ w) {
    int n = blockIdx.x;
    for (int k = threadIdx.x; k < CD; k += blockDim.x)
        g_BTf1[(size_t)n * CD + k] = __float2half(w[(size_t)k * FC1DIM + n]);
}

// ---------------- roi align -> fp16 A of conv1 ----------------
__global__ void roialign_kernel(const float* __restrict__ boxes) {
    __shared__ float swy[6], swx[6];
    __shared__ int sy0[6], sy1[6], sx0[6], sx1[6];
    int s = blockIdx.x;
    if (threadIdx.x == 0) {
        float x1, y1, x2, y2;
        if (s < BB) { x1 = 0.f; y1 = 0.f; x2 = (float)FF; y2 = (float)FF; }
        else {
            const float* bx = boxes + (size_t)(s - BB) * 4;
            x1 = bx[0]; y1 = bx[1]; x2 = bx[2]; y2 = bx[3];
        }
        float rw = fmaxf(x2 - x1, 1.f), rh = fmaxf(y2 - y1, 1.f);
        float scy = rh / 3.0f, scx = rw / 3.0f;
        for (int i = 0; i < 6; i++) {
            float pos = ((float)i + 0.5f) * 0.5f;
            float ys = fminf(fmaxf(y1 + pos * scy, 0.f), 13.f);
            float xs = fminf(fmaxf(x1 + pos * scx, 0.f), 13.f);
            float y0 = floorf(ys), x0 = floorf(xs);
            int y0i = (int)y0, x0i = (int)x0;
            sy0[i] = y0i; sx0[i] = x0i;
            sy1[i] = min(y0i + 1, 13); sx1[i] = min(x0i + 1, 13);
            swy[i] = ys - y0; swx[i] = xs - x0;
        }
    }
    __syncthreads();
    int b = (s < BB) ? s : (s - BB) / NN;
    const float* fm = g_fmapT + (size_t)b * SPAT * CC;
    for (int c = threadIdx.x; c < CC; c += blockDim.x) {
        float acc[9];
        #pragma unroll
        for (int k = 0; k < 9; k++) acc[k] = 0.f;
        #pragma unroll
        for (int sy = 0; sy < 6; sy++) {
            float wy = swy[sy];
            int y0 = sy0[sy], y1 = sy1[sy];
            #pragma unroll
            for (int sx = 0; sx < 6; sx++) {
                float wx = swx[sx];
                int x0 = sx0[sx], x1 = sx1[sx];
                float v00 = fm[(y0 * FF + x0) * CC + c];
                float v01 = fm[(y0 * FF + x1) * CC + c];
                float v10 = fm[(y1 * FF + x0) * CC + c];
                float v11 = fm[(y1 * FF + x1) * CC + c];
                float v = v00 * (1.f - wy) * (1.f - wx) + v01 * (1.f - wy) * wx
                        + v10 * wy * (1.f - wx) + v11 * wy * wx;
                acc[(sy >> 1) * 3 + (sx >> 1)] += v;
            }
        }
        #pragma unroll
        for (int k = 0; k < 9; k++)
            g_roiH[((size_t)s * 9 + k) * CC + c] = __float2half(acc[k] * 0.25f);
    }
}

// ---------------- fp16 tensor-core GEMM (mma.sync) ----------------
// C[M][N] = A[M][K] * BT[N][K]^T ; fp16 in, fp32 accumulate.
// CTA tile 128x128, K tile 64, 256 threads, 3-stage cp.async, conflict-free smem.
#define MODE_CONV      0   // v*scale[c&comask]+shift[..], leaky 0.1
#define MODE_BIAS      1   // v + shift[c]
#define MODE_BIAS_RELU 2   // relu(v + shift[c])

#define ROW_B  144                  // bytes per row: 64 halves + 8 pad -> 4r mod 32 banks
#define STAGE_BYTES (128 * ROW_B)   // 18432
#define SMEM_A_OFF  0
#define SMEM_B_OFF  (3 * STAGE_BYTES)
#define SMEM_TOTAL  (6 * STAGE_BYTES)   // 110592

__device__ __forceinline__ void cpasync16(uint32_t dst, const void* src) {
    asm volatile("cp.async.cg.shared.global [%0], [%1], 16;\n" :: "r"(dst), "l"(src));
}

template<int MODE>
__global__ void __launch_bounds__(256, 2) gemm_f16(
    const __half* __restrict__ A, const __half* __restrict__ BT,
    __half* __restrict__ Cout, int N_, int K,
    const float* __restrict__ scale, const float* __restrict__ shift, int comask)
{
    extern __shared__ char smem[];
    uint32_t sbase;
    asm("{ .reg .u64 t; cvta.to.shared.u64 t, %1; cvt.u32.u64 %0, t; }" : "=r"(sbase) : "l"(smem));
    const int tid = threadIdx.x, lane = tid & 31, wid = tid >> 5;
    const int wm = wid >> 2, wn = wid & 3;           // warp grid 2 x 4
    const int m0 = blockIdx.y * 128, n0 = blockIdx.x * 128;

    // staging: per 64-K stage, each matrix is 128 rows x 128B = 1024 x 16B chunks.
    // per thread: 4 chunks A + 4 chunks B.
    const __half* srcA[4];
    const __half* srcB[4];
    uint32_t dstA[4], dstB[4];
    #pragma unroll
    for (int r = 0; r < 4; r++) {
        int q = tid + r * 256;                 // 0..1023
        int row = q >> 3, seg = q & 7;
        srcA[r] = A + (size_t)(m0 + row) * K + seg * 8;
        srcB[r] = BT + (size_t)(n0 + row) * K + seg * 8;
        dstA[r] = sbase + SMEM_A_OFF + row * ROW_B + seg * 16;
        dstB[r] = sbase + SMEM_B_OFF + row * ROW_B + seg * 16;
    }

    float acc[4][4][4];
    #pragma unroll
    for (int mt = 0; mt < 4; mt++)
        #pragma unroll
        for (int nt = 0; nt < 4; nt++)
            #pragma unroll
            for (int i = 0; i < 4; i++) acc[mt][nt][i] = 0.f;

    const int KT = K >> 6;

    auto stage = [&](int s) {
        int slot;
        { int ss = s; slot = ss - (ss / 3) * 3; }
        int k0 = s << 6;
        #pragma unroll
        for (int r = 0; r < 4; r++)
            cpasync16(dstA[r] + slot * STAGE_BYTES, srcA[r] + k0);
        #pragma unroll
        for (int r = 0; r < 4; r++)
            cpasync16(dstB[r] + slot * STAGE_BYTES, srcB[r] + k0);
        asm volatile("cp.async.commit_group;\n");
    };

    stage(0); stage(1);

    // fragment base addresses (byte offsets inside one stage)
    const int arow = wm * 64 + (lane & 15);
    uint32_t aAddrBase = sbase + SMEM_A_OFF + arow * ROW_B + (lane >> 4) * 16;
    const int brow = wn * 32 + ((lane >> 3) & 1) * 8 + (lane & 7);
    uint32_t bAddrBase = sbase + SMEM_B_OFF + brow * ROW_B + (lane >> 4) * 16;

    int slot = 0;
    for (int c = 0; c < KT; c++) {
        asm volatile("cp.async.wait_group 1;\n");
        __syncthreads();
        if (c + 2 < KT) stage(c + 2);
        uint32_t aS = aAddrBase + slot * STAGE_BYTES;
        uint32_t bS = bAddrBase + slot * STAGE_BYTES;
        slot = (slot == 2) ? 0 : slot + 1;
        #pragma unroll
        for (int ks = 0; ks < 4; ks++) {
            uint32_t a[4][4], b[4][2];
            #pragma unroll
            for (int mt = 0; mt < 4; mt++) {
                asm volatile("ldmatrix.sync.aligned.m8n8.x4.shared.b16 {%0,%1,%2,%3},[%4];"
                    : "=r"(a[mt][0]), "=r"(a[mt][1]), "=r"(a[mt][2]), "=r"(a[mt][3])
                    : "r"(aS + mt * 16 * ROW_B + ks * 32));
            }
            #pragma unroll
            for (int nt2 = 0; nt2 < 2; nt2++) {
                uint32_t r0, r1, r2, r3;
                asm volatile("ldmatrix.sync.aligned.m8n8.x4.shared.b16 {%0,%1,%2,%3},[%4];"
                    : "=r"(r0), "=r"(r1), "=r"(r2), "=r"(r3)
                    : "r"(bS + nt2 * 16 * ROW_B + ks * 32));
                b[nt2 * 2 + 0][0] = r0; b[nt2 * 2 + 0][1] = r2;
                b[nt2 * 2 + 1][0] = r1; b[nt2 * 2 + 1][1] = r3;
            }
            #pragma unroll
            for (int mt = 0; mt < 4; mt++)
                #pragma unroll
                for (int nt = 0; nt < 4; nt++)
                    asm volatile("mma.sync.aligned.m16n8k16.row.col.f32.f16.f16.f32 "
                        "{%0,%1,%2,%3},{%4,%5,%6,%7},{%8,%9},{%0,%1,%2,%3};"
                        : "+f"(acc[mt][nt][0]), "+f"(acc[mt][nt][1]),
                          "+f"(acc[mt][nt][2]), "+f"(acc[mt][nt][3])
                        : "r"(a[mt][0]), "r"(a[mt][1]), "r"(a[mt][2]), "r"(a[mt][3]),
                          "r"(b[nt][0]), "r"(b[nt][1]));
        }
    }

    // epilogue: direct gmem stores
    #pragma unroll
    for (int mt = 0; mt < 4; mt++) {
        int r0 = m0 + wm * 64 + mt * 16 + (lane >> 2);
        #pragma unroll
        for (int nt = 0; nt < 4; nt++) {
            int c0 = n0 + wn * 32 + nt * 8 + (lane & 3) * 2;
            #pragma unroll
            for (int hh = 0; hh < 2; hh++) {
                int rr = r0 + hh * 8;
                float v0 = acc[mt][nt][hh * 2 + 0];
                float v1 = acc[mt][nt][hh * 2 + 1];
                if (MODE == MODE_CONV) {
                    int c0i = c0 & comask, c1i = (c0 + 1) & comask;
                    v0 = v0 * scale[c0i] + shift[c0i];
                    v1 = v1 * scale[c1i] + shift[c1i];
                    v0 = v0 > 0.f ? v0 : 0.1f * v0;
                    v1 = v1 > 0.f ? v1 : 0.1f * v1;
                } else {
                    v0 += shift[c0];
                    v1 += shift[c0 + 1];
                    if (MODE == MODE_BIAS_RELU) { v0 = fmaxf(v0, 0.f); v1 = fmaxf(v1, 0.f); }
                }
                *(__half2*)(Cout + (size_t)rr * N_ + c0) = __floats2half2_rn(v0, v1);
            }
        }
    }
}

// ---------------- scatter-add + im2col for conv1d ----------------
__global__ void buildbehavior_kernel(const int* __restrict__ person_idx) {
    int p = blockIdx.x / BB, b = blockIdx.x % BB;
    __shared__ int pid[NN];
    if (threadIdx.x < NN) pid[threadIdx.x] = person_idx[b * NN + threadIdx.x];
    __syncthreads();
    const __half* rowG = g_out2h + (size_t)b * N2;
    size_t base = (size_t)(p * BB + b) * K1D;
    for (int c = threadIdx.x; c < CD; c += blockDim.x) {
        int col = (c % 9) * C2 + (c / 9);
        float v = __half2float(rowG[col]);
        #pragma unroll
        for (int n = 0; n < NN; n++)
            if (pid[n] == p)
                v += __half2float(g_out2h[(size_t)(BB + b * NN + n) * N2 + col]);
        __half hv = __float2half(v);
        if (b + 1 < BB) g_A1d[(size_t)(p * BB + b + 1) * K1D + c] = hv;     // t=0
        g_A1d[base + CD + c] = hv;                                          // t=1
        if (b > 0) g_A1d[(size_t)(p * BB + b - 1) * K1D + 2 * CD + c] = hv; // t=2
        if (b == 0)      g_A1d[base + c] = __float2half(0.f);
        if (b == BB - 1) g_A1d[base + 2 * CD + c] = __float2half(0.f);
    }
}

// ---------------- pre-gather rows for fc1 ----------------
__global__ void gatherfeats_kernel(const int* __restrict__ person_idx) {
    int r = blockIdx.x;
    int b = r >> 4;
    int p = person_idx[r];
    const float4* src = (const float4*)(g_x1dh + (size_t)(p * BB + b) * CD);
    float4* dst = (float4*)(g_feats + (size_t)r * CD);
    for (int c = threadIdx.x; c < CD / 8; c += blockDim.x)
        dst[c] = src[c];
}

// ---------------- fc2 ----------------
__global__ void fc2_kernel(const float* __restrict__ w, const float* __restrict__ bias,
                           float* __restrict__ out) {
    __shared__ float red[4][32];
    int r = blockIdx.x;
    int t = threadIdx.x;
    int n = t & 31, kg = t >> 5;
    float acc = 0.f;
    if (n < NBCLS) {
        const __half* hr = g_hh + (size_t)r * FC1DIM + kg * 256;
        for (int j = 0; j < 256; j++)
            acc = fmaf(__half2float(hr[j]), w[(size_t)(kg * 256 + j) * NBCLS + n], acc);
    }
    red[kg][n] = acc;
    __syncthreads();
    if (kg == 0 && n < NBCLS)
        out[(size_t)r * NBCLS + n] = red[0][n] + red[1][n] + red[2][n] + red[3][n] + bias[n];
}

// ---------------- launch ----------------
extern "C" void kernel_launch(void* const* d_in, const int* in_sizes, int n_in,
                              void* d_out, int out_size) {
    const float* fmap      = (const float*)d_in[0];
    const float* boxes     = (const float*)d_in[1];
    const int*   person_idx= (const int*)  d_in[2];
    const float* conv1_w   = (const float*)d_in[3];
    const float* bn1_g     = (const float*)d_in[4];
    const float* bn1_b     = (const float*)d_in[5];
    const float* bn1_m     = (const float*)d_in[6];
    const float* bn1_v     = (const float*)d_in[7];
    const float* conv2_w   = (const float*)d_in[8];
    const float* bn2_g     = (const float*)d_in[9];
    const float* bn2_b     = (const float*)d_in[10];
    const float* bn2_m     = (const float*)d_in[11];
    const float* bn2_v     = (const float*)d_in[12];
    const float* conv1d_w  = (const float*)d_in[13];
    const float* conv1d_b  = (const float*)d_in[14];
    const float* fc1_w     = (const float*)d_in[15];
    const float* fc1_b     = (const float*)d_in[16];
    const float* fc2_w     = (const float*)d_in[17];
    const float* fc2_b     = (const float*)d_in[18];
    float* out = (float*)d_out;

    void *p_roiH, *p_BT1, *p_out1, *p_BT2, *p_out2, *p_A1d, *p_BT1d, *p_x1d,
         *p_feats, *p_BTf1, *p_hh, *p_sc1, *p_sh1, *p_sc2, *p_sh2;
    cudaGetSymbolAddress(&p_roiH, g_roiH);
    cudaGetSymbolAddress(&p_BT1,  g_BT1);
    cudaGetSymbolAddress(&p_out1, g_out1h);
    cudaGetSymbolAddress(&p_BT2,  g_BT2);
    cudaGetSymbolAddress(&p_out2, g_out2h);
    cudaGetSymbolAddress(&p_A1d,  g_A1d);
    cudaGetSymbolAddress(&p_BT1d, g_BT1d);
    cudaGetSymbolAddress(&p_x1d,  g_x1dh);
    cudaGetSymbolAddress(&p_feats, g_feats);
    cudaGetSymbolAddress(&p_BTf1, g_BTf1);
    cudaGetSymbolAddress(&p_hh,   g_hh);
    cudaGetSymbolAddress(&p_sc1,  g_scale1);
    cudaGetSymbolAddress(&p_sh1,  g_shift1);
    cudaGetSymbolAddress(&p_sc2,  g_scale2);
    cudaGetSymbolAddress(&p_sh2,  g_shift2);

    static bool inited = false;
    static cudaStream_t s1, s2;
    static cudaEvent_t evFork, evW1, evW2;
    if (!inited) {
        inited = true;
        cudaStreamCreateWithFlags(&s1, cudaStreamNonBlocking);
        cudaStreamCreateWithFlags(&s2, cudaStreamNonBlocking);
        cudaEventCreateWithFlags(&evFork, cudaEventDisableTiming);
        cudaEventCreateWithFlags(&evW1, cudaEventDisableTiming);
        cudaEventCreateWithFlags(&evW2, cudaEventDisableTiming);
        cudaFuncSetAttribute(gemm_f16<MODE_CONV>,
                             cudaFuncAttributeMaxDynamicSharedMemorySize, SMEM_TOTAL);
        cudaFuncSetAttribute(gemm_f16<MODE_BIAS>,
                             cudaFuncAttributeMaxDynamicSharedMemorySize, SMEM_TOTAL);
        cudaFuncSetAttribute(gemm_f16<MODE_BIAS_RELU>,
                             cudaFuncAttributeMaxDynamicSharedMemorySize, SMEM_TOTAL);
    }

    // ---- fork: weight prep on side streams ----
    bnfold_kernel<<<3, 256>>>(bn1_g, bn1_b, bn1_m, bn1_v, bn2_g, bn2_b, bn2_m, bn2_v);
    cudaEventRecord(evFork, 0);
    cudaStreamWaitEvent(s1, evFork, 0);
    cudaStreamWaitEvent(s2, evFork, 0);

    expand_conv_w<CC, C1><<<N1, 256, 0, s1>>>(conv1_w, (__half*)p_BT1);
    cudaEventRecord(evW1, s1);

    expand_conv_w<C1, C2><<<N2, 256, 0, s2>>>(conv2_w, (__half*)p_BT2);
    tw1d_kernel<<<CD, 256, 0, s2>>>(conv1d_w);
    twfc1_kernel<<<FC1DIM, 256, 0, s2>>>(fc1_w);
    cudaEventRecord(evW2, s2);

    // ---- main branch: fmap transpose -> roi align ----
    tfmap_kernel<<<dim3(7, 32, 64), dim3(32, 8)>>>(fmap);
    roialign_kernel<<<S_TOT, 256>>>(boxes);

    // ---- join W1, conv1: M=1152, N=4608, K=9216 ----
    cudaStreamWaitEvent(0, evW1, 0);
    gemm_f16<MODE_CONV><<<dim3(N1 / 128, S_PAD / 128), 256, SMEM_TOTAL>>>(
        (const __half*)p_roiH, (const __half*)p_BT1, (__half*)p_out1,
        N1, K1, (const float*)p_sc1, (const float*)p_sh1, C1 - 1);

    // ---- join W2, conv2: M=1152, N=2304, K=4608 ----
    cudaStreamWaitEvent(0, evW2, 0);
    gemm_f16<MODE_CONV><<<dim3(N2 / 128, S_PAD / 128), 256, SMEM_TOTAL>>>(
        (const __half*)p_out1, (const __half*)p_BT2, (__half*)p_out2,
        N2, K2, (const float*)p_sc2, (const float*)p_sh2, C2 - 1);

    // ---- scatter-add + im2col ----
    buildbehavior_kernel<<<PP * BB, 256>>>(person_idx);

    // ---- conv1d: M=1280, N=2304, K=6912 ----
    gemm_f16<MODE_BIAS><<<dim3(CD / 128, M1D / 128), 256, SMEM_TOTAL>>>(
        (const __half*)p_A1d, (const __half*)p_BT1d, (__half*)p_x1d,
        CD, K1D, nullptr, conv1d_b, 0);

    // ---- gather person rows ----
    gatherfeats_kernel<<<BB * NN, 256>>>(person_idx);

    // ---- fc1: M=1024, N=1024, K=2304 ----
    gemm_f16<MODE_BIAS_RELU><<<dim3(FC1DIM / 128, (BB * NN) / 128), 256, SMEM_TOTAL>>>(
        (const __half*)p_feats, (const __half*)p_BTf1, (__half*)p_hh,
        FC1DIM, CD, nullptr, fc1_b, 0);

    // ---- fc2 -> output ----
    fc2_kernel<<<BB * NN, 128>>>(fc2_w, fc2_b, out);
}

// round 9
// speedup vs baseline: 6.4783x; 1.1600x over previous
#include <cuda_runtime.h>
#include <cuda_fp16.h>
#include <cstdint>

// ---------------- problem constants ----------------
#define BB 64
#define NN 16
#define PP 20
#define NBCLS 30
#define CC 1024
#define FF 14
#define SPAT 196
#define S_TOT 1088
#define S_PAD 1152
#define C1 512
#define C2 256
#define CD 2304
#define K1 (9*CC)           // 9216
#define N1 (9*C1)           // 4608
#define K2 (9*C1)           // 4608
#define N2 (9*C2)           // 2304
#define K1D (3*CD)          // 6912
#define M1D (PP*BB)         // 1280
#define FC1DIM 1024

// ---------------- static device scratch ----------------
__device__ float  g_fmapT[BB*SPAT*CC];
__device__ __half g_roiH[(size_t)S_PAD*K1];
__device__ __half g_BT1[(size_t)N1*K1];
__device__ __half g_out1h[(size_t)S_PAD*N1];
__device__ __half g_BT2[(size_t)N2*K2];
__device__ __half g_out2h[(size_t)S_PAD*N2];
__device__ __half g_A1d[(size_t)M1D*K1D];
__device__ __half g_BT1d[(size_t)CD*K1D];
__device__ __half g_x1dh[(size_t)M1D*CD];
__device__ __half g_feats[(size_t)BB*NN*CD];
__device__ __half g_BTf1[(size_t)FC1DIM*CD];
__device__ __half g_hh[(size_t)BB*NN*FC1DIM];
__device__ float  g_scale1[C1], g_shift1[C1];
__device__ float  g_scale2[C2], g_shift2[C2];

// ---------------- BN folding ----------------
__global__ void bnfold_kernel(const float* g1, const float* b1, const float* m1, const float* v1,
                              const float* g2, const float* b2, const float* m2, const float* v2) {
    int t = blockIdx.x * blockDim.x + threadIdx.x;
    if (t < C1) {
        float s = g1[t] * rsqrtf(v1[t] + 1e-5f);
        g_scale1[t] = s;
        g_shift1[t] = b1[t] - m1[t] * s;
    } else if (t < C1 + C2) {
        int i = t - C1;
        float s = g2[i] * rsqrtf(v2[i] + 1e-5f);
        g_scale2[i] = s;
        g_shift2[i] = b2[i] - m2[i] * s;
    }
}

// ---------------- tiled fmap transpose [b][c][yx] -> [b][yx][c] ----------------
__global__ void tfmap_kernel(const float* __restrict__ fmap) {
    __shared__ float t[32][33];
    int b = blockIdx.z;
    int c0 = blockIdx.y * 32, yx0 = blockIdx.x * 32;
    int tx = threadIdx.x, ty = threadIdx.y;
    #pragma unroll
    for (int i = ty; i < 32; i += 8) {
        int yx = yx0 + tx;
        t[i][tx] = (yx < SPAT) ? fmap[((size_t)b * CC + c0 + i) * SPAT + yx] : 0.f;
    }
    __syncthreads();
    #pragma unroll
    for (int i = ty; i < 32; i += 8) {
        int yx = yx0 + i;
        if (yx < SPAT)
            g_fmapT[((size_t)b * SPAT + yx) * CC + c0 + tx] = t[tx][i];
    }
}

// ---------------- packed expanded conv weights ----------------
// For output position ko, only valid input positions ki are stored, front-packed:
// BT[n][kidx*CIN + ci] = w[co][ci][tap], n = ko*COUT+co, kidx enumerates valid ki.
// Row stride stays 9*CIN; the tail of each row is unused.
template<int CIN, int COUT>
__global__ void expand_conv_w(const float* __restrict__ w, __half* __restrict__ BT) {
    int n = blockIdx.x;
    int co = n & (COUT - 1), ko = n / COUT;
    int oy = ko / 3, ox = ko % 3;
    // valid tap list (same construction order as in gemm kernel)
    int taps[9]; int nv = 0;
    #pragma unroll
    for (int kiy = 0; kiy < 3; kiy++)
        #pragma unroll
        for (int kix = 0; kix < 3; kix++) {
            int ky = kiy - oy + 1, kx = kix - ox + 1;
            if ((unsigned)ky < 3u && (unsigned)kx < 3u) taps[nv++] = ky * 3 + kx;
        }
    const int Kp = nv * CIN;
    for (int k = threadIdx.x; k < Kp; k += blockDim.x) {
        int kidx = k / CIN, ci = k & (CIN - 1);
        BT[(size_t)n * (9 * CIN) + k] = __float2half(w[((size_t)co * CIN + ci) * 9 + taps[kidx]]);
    }
}

// conv1d weights: BT[co][t*CD+ci] = w[co][ci][t]
__global__ void tw1d_kernel(const float* __restrict__ w) {
    int co = blockIdx.x;
    for (int ci = threadIdx.x; ci < CD; ci += blockDim.x) {
        #pragma unroll
        for (int t = 0; t < 3; t++)
            g_BT1d[(size_t)co * K1D + t * CD + ci] = __float2half(w[((size_t)co * CD + ci) * 3 + t]);
    }
}

// fc1 weights: BT[n][k] = w[k][n]
__global__ void twfc1_kernel(const float* __restrict__ w) {
    int n = blockIdx.x;
    for (int k = threadIdx.x; k < CD; k += blockDim.x)
        g_BTf1[(size_t)n * CD + k] = __float2half(w[(size_t)k * FC1DIM + n]);
}

// ---------------- roi align -> fp16 A of conv1 ----------------
__global__ void roialign_kernel(const float* __restrict__ boxes) {
    __shared__ float swy[6], swx[6];
    __shared__ int sy0[6], sy1[6], sx0[6], sx1[6];
    int s = blockIdx.x;
    if (threadIdx.x == 0) {
        float x1, y1, x2, y2;
        if (s < BB) { x1 = 0.f; y1 = 0.f; x2 = (float)FF; y2 = (float)FF; }
        else {
            const float* bx = boxes + (size_t)(s - BB) * 4;
            x1 = bx[0]; y1 = bx[1]; x2 = bx[2]; y2 = bx[3];
        }
        float rw = fmaxf(x2 - x1, 1.f), rh = fmaxf(y2 - y1, 1.f);
        float scy = rh / 3.0f, scx = rw / 3.0f;
        for (int i = 0; i < 6; i++) {
            float pos = ((float)i + 0.5f) * 0.5f;
            float ys = fminf(fmaxf(y1 + pos * scy, 0.f), 13.f);
            float xs = fminf(fmaxf(x1 + pos * scx, 0.f), 13.f);
            float y0 = floorf(ys), x0 = floorf(xs);
            int y0i = (int)y0, x0i = (int)x0;
            sy0[i] = y0i; sx0[i] = x0i;
            sy1[i] = min(y0i + 1, 13); sx1[i] = min(x0i + 1, 13);
            swy[i] = ys - y0; swx[i] = xs - x0;
        }
    }
    __syncthreads();
    int b = (s < BB) ? s : (s - BB) / NN;
    const float* fm = g_fmapT + (size_t)b * SPAT * CC;
    for (int c = threadIdx.x; c < CC; c += blockDim.x) {
        float acc[9];
        #pragma unroll
        for (int k = 0; k < 9; k++) acc[k] = 0.f;
        #pragma unroll
        for (int sy = 0; sy < 6; sy++) {
            float wy = swy[sy];
            int y0 = sy0[sy], y1 = sy1[sy];
            #pragma unroll
            for (int sx = 0; sx < 6; sx++) {
                float wx = swx[sx];
                int x0 = sx0[sx], x1 = sx1[sx];
                float v00 = fm[(y0 * FF + x0) * CC + c];
                float v01 = fm[(y0 * FF + x1) * CC + c];
                float v10 = fm[(y1 * FF + x0) * CC + c];
                float v11 = fm[(y1 * FF + x1) * CC + c];
                float v = v00 * (1.f - wy) * (1.f - wx) + v01 * (1.f - wy) * wx
                        + v10 * wy * (1.f - wx) + v11 * wy * wx;
                acc[(sy >> 1) * 3 + (sx >> 1)] += v;
            }
        }
        #pragma unroll
        for (int k = 0; k < 9; k++)
            g_roiH[((size_t)s * 9 + k) * CC + c] = __float2half(acc[k] * 0.25f);
    }
}

// ---------------- fp16 tensor-core GEMM (mma.sync) ----------------
// C[M][N] = A[M][K] * BT[N][K]^T ; fp16 in, fp32 accumulate.
// CTA tile 128x128, K tile 64, 256 threads, 3-stage cp.async.
// Conv mode (ntpko>0): N-block belongs to output position ko = bx/ntpko;
// K-loop runs only over valid input positions (table s_kmap), A indexed via table,
// B is front-packed.
#define MODE_CONV      0
#define MODE_BIAS      1
#define MODE_BIAS_RELU 2

#define ROW_B  144
#define STAGE_BYTES (128 * ROW_B)   // 18432
#define SMEM_A_OFF  0
#define SMEM_B_OFF  (3 * STAGE_BYTES)
#define SMEM_TOTAL  (6 * STAGE_BYTES)   // 110592

__device__ __forceinline__ void cpasync16(uint32_t dst, const void* src) {
    asm volatile("cp.async.cg.shared.global [%0], [%1], 16;\n" :: "r"(dst), "l"(src));
}

template<int MODE>
__global__ void __launch_bounds__(256, 2) gemm_f16(
    const __half* __restrict__ A, const __half* __restrict__ BT,
    __half* __restrict__ Cout, int N_, int K,
    const float* __restrict__ scale, const float* __restrict__ shift, int comask,
    int ntpko, int cin_l2)
{
    extern __shared__ char smem[];
    __shared__ int s_kmap[10];           // [0..8] valid ki list, [9] = KT
    uint32_t sbase;
    asm("{ .reg .u64 t; cvta.to.shared.u64 t, %1; cvt.u32.u64 %0, t; }" : "=r"(sbase) : "l"(smem));
    const int tid = threadIdx.x, lane = tid & 31, wid = tid >> 5;
    const int wm = wid >> 2, wn = wid & 3;
    const int m0 = blockIdx.y * 128, n0 = blockIdx.x * 128;

    if (tid == 0) {
        if (ntpko) {
            int ko = blockIdx.x / ntpko;
            int oy = ko / 3, ox = ko % 3;
            int nv = 0;
            #pragma unroll
            for (int kiy = 0; kiy < 3; kiy++)
                #pragma unroll
                for (int kix = 0; kix < 3; kix++) {
                    int ky = kiy - oy + 1, kx = kix - ox + 1;
                    if ((unsigned)ky < 3u && (unsigned)kx < 3u)
                        s_kmap[nv++] = kiy * 3 + kix;
                }
            s_kmap[9] = nv << cin_l2;
        } else {
            s_kmap[9] = K >> 6;
        }
    }
    __syncthreads();
    const int KT = s_kmap[9];

    // per-thread staging coords
    const __half* baseA[4];
    const __half* baseB[4];
    uint32_t dstA[4], dstB[4];
    #pragma unroll
    for (int r = 0; r < 4; r++) {
        int q = tid + r * 256;
        int row = q >> 3, seg = q & 7;
        baseA[r] = A + (size_t)(m0 + row) * K + seg * 8;
        baseB[r] = BT + (size_t)(n0 + row) * K + seg * 8;
        dstA[r] = sbase + SMEM_A_OFF + row * ROW_B + seg * 16;
        dstB[r] = sbase + SMEM_B_OFF + row * ROW_B + seg * 16;
    }

    float acc[4][4][4];
    #pragma unroll
    for (int mt = 0; mt < 4; mt++)
        #pragma unroll
        for (int nt = 0; nt < 4; nt++)
            #pragma unroll
            for (int i = 0; i < 4; i++) acc[mt][nt][i] = 0.f;

    auto stage = [&](int s) {
        int slot = s - (s / 3) * 3;
        int a_k0;
        if (ntpko) {
            int ki = s_kmap[s >> cin_l2];
            a_k0 = (ki << (cin_l2 + 6)) + ((s & ((1 << cin_l2) - 1)) << 6);
        } else {
            a_k0 = s << 6;
        }
        int b_k0 = s << 6;
        #pragma unroll
        for (int r = 0; r < 4; r++)
            cpasync16(dstA[r] + slot * STAGE_BYTES, baseA[r] + a_k0);
        #pragma unroll
        for (int r = 0; r < 4; r++)
            cpasync16(dstB[r] + slot * STAGE_BYTES, baseB[r] + b_k0);
        asm volatile("cp.async.commit_group;\n");
    };

    stage(0);
    if (KT > 1) stage(1);

    const int arow = wm * 64 + (lane & 15);
    uint32_t aAddrBase = sbase + SMEM_A_OFF + arow * ROW_B + (lane >> 4) * 16;
    const int brow = wn * 32 + ((lane >> 3) & 1) * 8 + (lane & 7);
    uint32_t bAddrBase = sbase + SMEM_B_OFF + brow * ROW_B + (lane >> 4) * 16;

    int slot = 0;
    for (int c = 0; c < KT; c++) {
        asm volatile("cp.async.wait_group 1;\n");
        __syncthreads();
        if (c + 2 < KT) stage(c + 2);
        uint32_t aS = aAddrBase + slot * STAGE_BYTES;
        uint32_t bS = bAddrBase + slot * STAGE_BYTES;
        slot = (slot == 2) ? 0 : slot + 1;
        #pragma unroll
        for (int ks = 0; ks < 4; ks++) {
            uint32_t a[4][4], b[4][2];
            #pragma unroll
            for (int mt = 0; mt < 4; mt++) {
                asm volatile("ldmatrix.sync.aligned.m8n8.x4.shared.b16 {%0,%1,%2,%3},[%4];"
                    : "=r"(a[mt][0]), "=r"(a[mt][1]), "=r"(a[mt][2]), "=r"(a[mt][3])
                    : "r"(aS + mt * 16 * ROW_B + ks * 32));
            }
            #pragma unroll
            for (int nt2 = 0; nt2 < 2; nt2++) {
                uint32_t r0, r1, r2, r3;
                asm volatile("ldmatrix.sync.aligned.m8n8.x4.shared.b16 {%0,%1,%2,%3},[%4];"
                    : "=r"(r0), "=r"(r1), "=r"(r2), "=r"(r3)
                    : "r"(bS + nt2 * 16 * ROW_B + ks * 32));
                b[nt2 * 2 + 0][0] = r0; b[nt2 * 2 + 0][1] = r2;
                b[nt2 * 2 + 1][0] = r1; b[nt2 * 2 + 1][1] = r3;
            }
            #pragma unroll
            for (int mt = 0; mt < 4; mt++)
                #pragma unroll
                for (int nt = 0; nt < 4; nt++)
                    asm volatile("mma.sync.aligned.m16n8k16.row.col.f32.f16.f16.f32 "
                        "{%0,%1,%2,%3},{%4,%5,%6,%7},{%8,%9},{%0,%1,%2,%3};"
                        : "+f"(acc[mt][nt][0]), "+f"(acc[mt][nt][1]),
                          "+f"(acc[mt][nt][2]), "+f"(acc[mt][nt][3])
                        : "r"(a[mt][0]), "r"(a[mt][1]), "r"(a[mt][2]), "r"(a[mt][3]),
                          "r"(b[nt][0]), "r"(b[nt][1]));
        }
    }

    // epilogue
    #pragma unroll
    for (int mt = 0; mt < 4; mt++) {
        int r0 = m0 + wm * 64 + mt * 16 + (lane >> 2);
        #pragma unroll
        for (int nt = 0; nt < 4; nt++) {
            int c0 = n0 + wn * 32 + nt * 8 + (lane & 3) * 2;
            #pragma unroll
            for (int hh = 0; hh < 2; hh++) {
                int rr = r0 + hh * 8;
                float v0 = acc[mt][nt][hh * 2 + 0];
                float v1 = acc[mt][nt][hh * 2 + 1];
                if (MODE == MODE_CONV) {
                    int c0i = c0 & comask, c1i = (c0 + 1) & comask;
                    v0 = v0 * scale[c0i] + shift[c0i];
                    v1 = v1 * scale[c1i] + shift[c1i];
                    v0 = v0 > 0.f ? v0 : 0.1f * v0;
                    v1 = v1 > 0.f ? v1 : 0.1f * v1;
                } else {
                    v0 += shift[c0];
                    v1 += shift[c0 + 1];
                    if (MODE == MODE_BIAS_RELU) { v0 = fmaxf(v0, 0.f); v1 = fmaxf(v1, 0.f); }
                }
                *(__half2*)(Cout + (size_t)rr * N_ + c0) = __floats2half2_rn(v0, v1);
            }
        }
    }
}

// ---------------- scatter-add + im2col for conv1d ----------------
__global__ void buildbehavior_kernel(const int* __restrict__ person_idx) {
    int p = blockIdx.x / BB, b = blockIdx.x % BB;
    __shared__ int pid[NN];
    if (threadIdx.x < NN) pid[threadIdx.x] = person_idx[b * NN + threadIdx.x];
    __syncthreads();
    const __half* rowG = g_out2h + (size_t)b * N2;
    size_t base = (size_t)(p * BB + b) * K1D;
    for (int c = threadIdx.x; c < CD; c += blockDim.x) {
        int col = (c % 9) * C2 + (c / 9);
        float v = __half2float(rowG[col]);
        #pragma unroll
        for (int n = 0; n < NN; n++)
            if (pid[n] == p)
                v += __half2float(g_out2h[(size_t)(BB + b * NN + n) * N2 + col]);
        __half hv = __float2half(v);
        if (b + 1 < BB) g_A1d[(size_t)(p * BB + b + 1) * K1D + c] = hv;     // t=0
        g_A1d[base + CD + c] = hv;                                          // t=1
        if (b > 0) g_A1d[(size_t)(p * BB + b - 1) * K1D + 2 * CD + c] = hv; // t=2
        if (b == 0)      g_A1d[base + c] = __float2half(0.f);
        if (b == BB - 1) g_A1d[base + 2 * CD + c] = __float2half(0.f);
    }
}

// ---------------- pre-gather rows for fc1 ----------------
__global__ void gatherfeats_kernel(const int* __restrict__ person_idx) {
    int r = blockIdx.x;
    int b = r >> 4;
    int p = person_idx[r];
    const float4* src = (const float4*)(g_x1dh + (size_t)(p * BB + b) * CD);
    float4* dst = (float4*)(g_feats + (size_t)r * CD);
    for (int c = threadIdx.x; c < CD / 8; c += blockDim.x)
        dst[c] = src[c];
}

// ---------------- fc2 ----------------
__global__ void fc2_kernel(const float* __restrict__ w, const float* __restrict__ bias,
                           float* __restrict__ out) {
    __shared__ float red[4][32];
    int r = blockIdx.x;
    int t = threadIdx.x;
    int n = t & 31, kg = t >> 5;
    float acc = 0.f;
    if (n < NBCLS) {
        const __half* hr = g_hh + (size_t)r * FC1DIM + kg * 256;
        for (int j = 0; j < 256; j++)
            acc = fmaf(__half2float(hr[j]), w[(size_t)(kg * 256 + j) * NBCLS + n], acc);
    }
    red[kg][n] = acc;
    __syncthreads();
    if (kg == 0 && n < NBCLS)
        out[(size_t)r * NBCLS + n] = red[0][n] + red[1][n] + red[2][n] + red[3][n] + bias[n];
}

// ---------------- launch ----------------
extern "C" void kernel_launch(void* const* d_in, const int* in_sizes, int n_in,
                              void* d_out, int out_size) {
    const float* fmap      = (const float*)d_in[0];
    const float* boxes     = (const float*)d_in[1];
    const int*   person_idx= (const int*)  d_in[2];
    const float* conv1_w   = (const float*)d_in[3];
    const float* bn1_g     = (const float*)d_in[4];
    const float* bn1_b     = (const float*)d_in[5];
    const float* bn1_m     = (const float*)d_in[6];
    const float* bn1_v     = (const float*)d_in[7];
    const float* conv2_w   = (const float*)d_in[8];
    const float* bn2_g     = (const float*)d_in[9];
    const float* bn2_b     = (const float*)d_in[10];
    const float* bn2_m     = (const float*)d_in[11];
    const float* bn2_v     = (const float*)d_in[12];
    const float* conv1d_w  = (const float*)d_in[13];
    const float* conv1d_b  = (const float*)d_in[14];
    const float* fc1_w     = (const float*)d_in[15];
    const float* fc1_b     = (const float*)d_in[16];
    const float* fc2_w     = (const float*)d_in[17];
    const float* fc2_b     = (const float*)d_in[18];
    float* out = (float*)d_out;

    void *p_roiH, *p_BT1, *p_out1, *p_BT2, *p_out2, *p_A1d, *p_BT1d, *p_x1d,
         *p_feats, *p_BTf1, *p_hh, *p_sc1, *p_sh1, *p_sc2, *p_sh2;
    cudaGetSymbolAddress(&p_roiH, g_roiH);
    cudaGetSymbolAddress(&p_BT1,  g_BT1);
    cudaGetSymbolAddress(&p_out1, g_out1h);
    cudaGetSymbolAddress(&p_BT2,  g_BT2);
    cudaGetSymbolAddress(&p_out2, g_out2h);
    cudaGetSymbolAddress(&p_A1d,  g_A1d);
    cudaGetSymbolAddress(&p_BT1d, g_BT1d);
    cudaGetSymbolAddress(&p_x1d,  g_x1dh);
    cudaGetSymbolAddress(&p_feats, g_feats);
    cudaGetSymbolAddress(&p_BTf1, g_BTf1);
    cudaGetSymbolAddress(&p_hh,   g_hh);
    cudaGetSymbolAddress(&p_sc1,  g_scale1);
    cudaGetSymbolAddress(&p_sh1,  g_shift1);
    cudaGetSymbolAddress(&p_sc2,  g_scale2);
    cudaGetSymbolAddress(&p_sh2,  g_shift2);

    static bool inited = false;
    static cudaStream_t s1, s2;
    static cudaEvent_t evFork, evW1, evW2;
    if (!inited) {
        inited = true;
        cudaStreamCreateWithFlags(&s1, cudaStreamNonBlocking);
        cudaStreamCreateWithFlags(&s2, cudaStreamNonBlocking);
        cudaEventCreateWithFlags(&evFork, cudaEventDisableTiming);
        cudaEventCreateWithFlags(&evW1, cudaEventDisableTiming);
        cudaEventCreateWithFlags(&evW2, cudaEventDisableTiming);
        cudaFuncSetAttribute(gemm_f16<MODE_CONV>,
                             cudaFuncAttributeMaxDynamicSharedMemorySize, SMEM_TOTAL);
        cudaFuncSetAttribute(gemm_f16<MODE_BIAS>,
                             cudaFuncAttributeMaxDynamicSharedMemorySize, SMEM_TOTAL);
        cudaFuncSetAttribute(gemm_f16<MODE_BIAS_RELU>,
                             cudaFuncAttributeMaxDynamicSharedMemorySize, SMEM_TOTAL);
    }

    // ---- fork: weight prep on side streams ----
    bnfold_kernel<<<3, 256>>>(bn1_g, bn1_b, bn1_m, bn1_v, bn2_g, bn2_b, bn2_m, bn2_v);
    cudaEventRecord(evFork, 0);
    cudaStreamWaitEvent(s1, evFork, 0);
    cudaStreamWaitEvent(s2, evFork, 0);

    expand_conv_w<CC, C1><<<N1, 256, 0, s1>>>(conv1_w, (__half*)p_BT1);
    cudaEventRecord(evW1, s1);

    expand_conv_w<C1, C2><<<N2, 256, 0, s2>>>(conv2_w, (__half*)p_BT2);
    tw1d_kernel<<<CD, 256, 0, s2>>>(conv1d_w);
    twfc1_kernel<<<FC1DIM, 256, 0, s2>>>(fc1_w);
    cudaEventRecord(evW2, s2);

    // ---- main branch: fmap transpose -> roi align ----
    tfmap_kernel<<<dim3(7, 32, 64), dim3(32, 8)>>>(fmap);
    roialign_kernel<<<S_TOT, 256>>>(boxes);

    // ---- join W1, conv1: M=1152, N=4608, Kpacked = nv(ko)*1024 ----
    cudaStreamWaitEvent(0, evW1, 0);
    gemm_f16<MODE_CONV><<<dim3(N1 / 128, S_PAD / 128), 256, SMEM_TOTAL>>>(
        (const __half*)p_roiH, (const __half*)p_BT1, (__half*)p_out1,
        N1, K1, (const float*)p_sc1, (const float*)p_sh1, C1 - 1,
        /*ntpko=*/C1 / 128, /*cin_l2=*/4);

    // ---- join W2, conv2: M=1152, N=2304, Kpacked = nv(ko)*512 ----
    cudaStreamWaitEvent(0, evW2, 0);
    gemm_f16<MODE_CONV><<<dim3(N2 / 128, S_PAD / 128), 256, SMEM_TOTAL>>>(
        (const __half*)p_out1, (const __half*)p_BT2, (__half*)p_out2,
        N2, K2, (const float*)p_sc2, (const float*)p_sh2, C2 - 1,
        /*ntpko=*/C2 / 128, /*cin_l2=*/3);

    // ---- scatter-add + im2col ----
    buildbehavior_kernel<<<PP * BB, 256>>>(person_idx);

    // ---- conv1d: M=1280, N=2304, K=6912 ----
    gemm_f16<MODE_BIAS><<<dim3(CD / 128, M1D / 128), 256, SMEM_TOTAL>>>(
        (const __half*)p_A1d, (const __half*)p_BT1d, (__half*)p_x1d,
        CD, K1D, nullptr, conv1d_b, 0, 0, 0);

    // ---- gather person rows ----
    gatherfeats_kernel<<<BB * NN, 256>>>(person_idx);

    // ---- fc1: M=1024, N=1024, K=2304 ----
    gemm_f16<MODE_BIAS_RELU><<<dim3(FC1DIM / 128, (BB * NN) / 128), 256, SMEM_TOTAL>>>(
        (const __half*)p_feats, (const __half*)p_BTf1, (__half*)p_hh,
        FC1DIM, CD, nullptr, fc1_b, 0, 0, 0);

    // ---- fc2 -> output ----
    fc2_kernel<<<BB * NN, 128>>>(fc2_w, fc2_b, out);
}

// round 11
// speedup vs baseline: 7.2306x; 1.1161x over previous
#include <cuda_runtime.h>
#include <cuda_fp16.h>
#include <cstdint>

// ---------------- problem constants ----------------
#define BB 64
#define NN 16
#define PP 20
#define NBCLS 30
#define CC 1024
#define FF 14
#define SPAT 196
#define S_TOT 1088
#define S_PAD 1152
#define C1 512
#define C2 256
#define CD 2304
#define K1 (9*CC)           // 9216
#define N1 (9*C1)           // 4608
#define K2 (9*C1)           // 4608
#define N2 (9*C2)           // 2304
#define K1D (3*CD)          // 6912
#define M1D (PP*BB)         // 1280
#define FC1DIM 1024
#define GMAX 296            // 148 SMs x 2 CTA

// ---------------- static device scratch ----------------
__device__ float  g_fmapT[BB*SPAT*CC];
__device__ __half g_roiH[(size_t)S_PAD*K1];
__device__ __half g_BT1[(size_t)N1*K1];
__device__ __half g_out1h[(size_t)S_PAD*N1];
__device__ __half g_BT2[(size_t)N2*K2];
__device__ __half g_out2h[(size_t)S_PAD*N2];
__device__ __half g_A1d[(size_t)M1D*K1D];
__device__ __half g_BT1d[(size_t)CD*K1D];
__device__ __half g_feats[(size_t)BB*NN*CD];
__device__ __half g_BTf1[(size_t)FC1DIM*CD];
__device__ __half g_hh[(size_t)BB*NN*FC1DIM];
__device__ float  g_scale1[C1], g_shift1[C1];
__device__ float  g_scale2[C2], g_shift2[C2];
__device__ int    g_rowmap[BB*NN];

// ko order by descending valid-tap count: center(9), edges(6), corners(4)
__constant__ int c_korder[9] = {4, 1, 3, 5, 7, 0, 2, 6, 8};

// ---------------- BN folding ----------------
__global__ void bnfold_kernel(const float* g1, const float* b1, const float* m1, const float* v1,
                              const float* g2, const float* b2, const float* m2, const float* v2) {
    int t = blockIdx.x * blockDim.x + threadIdx.x;
    if (t < C1) {
        float s = g1[t] * rsqrtf(v1[t] + 1e-5f);
        g_scale1[t] = s;
        g_shift1[t] = b1[t] - m1[t] * s;
    } else if (t < C1 + C2) {
        int i = t - C1;
        float s = g2[i] * rsqrtf(v2[i] + 1e-5f);
        g_scale2[i] = s;
        g_shift2[i] = b2[i] - m2[i] * s;
    }
}

// ---------------- tiled fmap transpose [b][c][yx] -> [b][yx][c] ----------------
__global__ void tfmap_kernel(const float* __restrict__ fmap) {
    __shared__ float t[32][33];
    int b = blockIdx.z;
    int c0 = blockIdx.y * 32, yx0 = blockIdx.x * 32;
    int tx = threadIdx.x, ty = threadIdx.y;
    #pragma unroll
    for (int i = ty; i < 32; i += 8) {
        int yx = yx0 + tx;
        t[i][tx] = (yx < SPAT) ? fmap[((size_t)b * CC + c0 + i) * SPAT + yx] : 0.f;
    }
    __syncthreads();
    #pragma unroll
    for (int i = ty; i < 32; i += 8) {
        int yx = yx0 + i;
        if (yx < SPAT)
            g_fmapT[((size_t)b * SPAT + yx) * CC + c0 + tx] = t[tx][i];
    }
}

// ---------------- packed expanded conv weights ----------------
template<int CIN, int COUT>
__global__ void expand_conv_w(const float* __restrict__ w, __half* __restrict__ BT) {
    int n = blockIdx.x;
    int co = n & (COUT - 1), ko = n / COUT;
    int oy = ko / 3, ox = ko % 3;
    int taps[9]; int nv = 0;
    #pragma unroll
    for (int kiy = 0; kiy < 3; kiy++)
        #pragma unroll
        for (int kix = 0; kix < 3; kix++) {
            int ky = kiy - oy + 1, kx = kix - ox + 1;
            if ((unsigned)ky < 3u && (unsigned)kx < 3u) taps[nv++] = ky * 3 + kx;
        }
    const int Kp = nv * CIN;
    for (int k = threadIdx.x; k < Kp; k += blockDim.x) {
        int kidx = k / CIN, ci = k & (CIN - 1);
        BT[(size_t)n * (9 * CIN) + k] = __float2half(w[((size_t)co * CIN + ci) * 9 + taps[kidx]]);
    }
}

// conv1d weights: BT[co][t*CD+ci] = w[co][ci][t]
__global__ void tw1d_kernel(const float* __restrict__ w) {
    int co = blockIdx.x;
    for (int ci = threadIdx.x; ci < CD; ci += blockDim.x) {
        #pragma unroll
        for (int t = 0; t < 3; t++)
            g_BT1d[(size_t)co * K1D + t * CD + ci] = __float2half(w[((size_t)co * CD + ci) * 3 + t]);
    }
}

// fc1 weights: BT[n][k] = w[k][n]
__global__ void twfc1_kernel(const float* __restrict__ w) {
    int n = blockIdx.x;
    for (int k = threadIdx.x; k < CD; k += blockDim.x)
        g_BTf1[(size_t)n * CD + k] = __float2half(w[(size_t)k * FC1DIM + n]);
}

// rowmap: output row r of conv1d = behavior row (pid[r]*64 + b)
__global__ void rowmap_kernel(const int* __restrict__ person_idx) {
    int r = blockIdx.x * blockDim.x + threadIdx.x;
    if (r < BB * NN)
        g_rowmap[r] = person_idx[r] * BB + (r >> 4);
}

// ---------------- roi align -> fp16 A of conv1 ----------------
__global__ void roialign_kernel(const float* __restrict__ boxes) {
    __shared__ float swy[6], swx[6];
    __shared__ int sy0[6], sy1[6], sx0[6], sx1[6];
    int s = blockIdx.x;
    if (threadIdx.x == 0) {
        float x1, y1, x2, y2;
        if (s < BB) { x1 = 0.f; y1 = 0.f; x2 = (float)FF; y2 = (float)FF; }
        else {
            const float* bx = boxes + (size_t)(s - BB) * 4;
            x1 = bx[0]; y1 = bx[1]; x2 = bx[2]; y2 = bx[3];
        }
        float rw = fmaxf(x2 - x1, 1.f), rh = fmaxf(y2 - y1, 1.f);
        float scy = rh / 3.0f, scx = rw / 3.0f;
        for (int i = 0; i < 6; i++) {
            float pos = ((float)i + 0.5f) * 0.5f;
            float ys = fminf(fmaxf(y1 + pos * scy, 0.f), 13.f);
            float xs = fminf(fmaxf(x1 + pos * scx, 0.f), 13.f);
            float y0 = floorf(ys), x0 = floorf(xs);
            int y0i = (int)y0, x0i = (int)x0;
            sy0[i] = y0i; sx0[i] = x0i;
            sy1[i] = min(y0i + 1, 13); sx1[i] = min(x0i + 1, 13);
            swy[i] = ys - y0; swx[i] = xs - x0;
        }
    }
    __syncthreads();
    int b = (s < BB) ? s : (s - BB) / NN;
    const float* fm = g_fmapT + (size_t)b * SPAT * CC;
    for (int c = threadIdx.x; c < CC; c += blockDim.x) {
        float acc[9];
        #pragma unroll
        for (int k = 0; k < 9; k++) acc[k] = 0.f;
        #pragma unroll
        for (int sy = 0; sy < 6; sy++) {
            float wy = swy[sy];
            int y0 = sy0[sy], y1 = sy1[sy];
            #pragma unroll
            for (int sx = 0; sx < 6; sx++) {
                float wx = swx[sx];
                int x0 = sx0[sx], x1 = sx1[sx];
                float v00 = fm[(y0 * FF + x0) * CC + c];
                float v01 = fm[(y0 * FF + x1) * CC + c];
                float v10 = fm[(y1 * FF + x0) * CC + c];
                float v11 = fm[(y1 * FF + x1) * CC + c];
                float v = v00 * (1.f - wy) * (1.f - wx) + v01 * (1.f - wy) * wx
                        + v10 * wy * (1.f - wx) + v11 * wy * wx;
                acc[(sy >> 1) * 3 + (sx >> 1)] += v;
            }
        }
        #pragma unroll
        for (int k = 0; k < 9; k++)
            g_roiH[((size_t)s * 9 + k) * CC + c] = __float2half(acc[k] * 0.25f);
    }
}

// ---------------- fp16 tensor-core GEMM (mma.sync), persistent LPT tiles ----------------
// C[M][N] = A[M][K] * BT[N][K]^T ; fp16 in, fp32 accumulate.
// CTA tile 128x128, K tile 64, 256 threads, 3-stage cp.async.
// Tiles are enumerated in sorted (longest-K-first) order; slot s computes tile s
// and, if in range, tile 2G-1-s (LPT pairing: shortest tiles pair together).
// Conv mode (ntpko>0): tile group g maps to ko=c_korder[g]; K loop covers only
// valid input positions (s_kmap), B rows are front-packed.
// rowmap (optional): A row indirection table for gathered-M GEMMs.
#define MODE_CONV      0
#define MODE_BIAS      1
#define MODE_BIAS_RELU 2

#define ROW_B  144
#define STAGE_BYTES (128 * ROW_B)   // 18432
#define SMEM_A_OFF  0
#define SMEM_B_OFF  (3 * STAGE_BYTES)
#define SMEM_TOTAL  (6 * STAGE_BYTES)   // 110592

__device__ __forceinline__ void cpasync16(uint32_t dst, const void* src) {
    asm volatile("cp.async.cg.shared.global [%0], [%1], 16;\n" :: "r"(dst), "l"(src));
}

template<int MODE>
__global__ void __launch_bounds__(256, 2) gemm_f16(
    const __half* __restrict__ A, const __half* __restrict__ BT,
    __half* __restrict__ Cout, int N_, int K,
    const float* __restrict__ scale, const float* __restrict__ shift, int comask,
    int ntiles, int nbx, int ntpko, int cin_l2, const int* __restrict__ rowmap)
{
    extern __shared__ char smem[];
    __shared__ int s_kmap[10];
    uint32_t sbase;
    asm("{ .reg .u64 t; cvta.to.shared.u64 t, %1; cvt.u32.u64 %0, t; }" : "=r"(sbase) : "l"(smem));
    const int tid = threadIdx.x, lane = tid & 31, wid = tid >> 5;
    const int wm = wid >> 2, wn = wid & 3;
    const int G = gridDim.x;

    for (int which = 0; which < 2; which++) {
        int u;
        if (which == 0) {
            u = blockIdx.x;
        } else {
            u = 2 * G - 1 - blockIdx.x;
            if (u < G || u >= ntiles) break;
        }

        // ---- decode tile u -> m0, n0, kmap ----
        int m0, n0;
        __syncthreads();                       // protect smem/s_kmap from prev tile
        if (ntpko) {
            int gsz = ntpko * nbx;             // nbx carries NBY (M blocks) in conv mode
            int g = u / gsz;
            int rem = u - g * gsz;
            int ko = c_korder[g];
            int by = rem / ntpko;
            int nx = rem - by * ntpko;
            m0 = by << 7;
            n0 = (ko * ntpko + nx) << 7;
            if (tid == 0) {
                int oy = ko / 3, ox = ko % 3;
                int nv = 0;
                #pragma unroll
                for (int kiy = 0; kiy < 3; kiy++)
                    #pragma unroll
                    for (int kix = 0; kix < 3; kix++) {
                        int ky = kiy - oy + 1, kx = kix - ox + 1;
                        if ((unsigned)ky < 3u && (unsigned)kx < 3u)
                            s_kmap[nv++] = kiy * 3 + kix;
                    }
                s_kmap[9] = nv << cin_l2;
            }
        } else {
            int by = u / nbx;
            m0 = by << 7;
            n0 = (u - by * nbx) << 7;
            if (tid == 0) s_kmap[9] = K >> 6;
        }
        __syncthreads();
        const int KT = s_kmap[9];

        // ---- per-thread staging coords ----
        const __half* baseA[4];
        const __half* baseB[4];
        uint32_t dstA[4], dstB[4];
        #pragma unroll
        for (int r = 0; r < 4; r++) {
            int q = tid + r * 256;
            int row = q >> 3, seg = q & 7;
            int gr = m0 + row;
            if (rowmap) gr = rowmap[gr];
            baseA[r] = A + (size_t)gr * K + seg * 8;
            baseB[r] = BT + (size_t)(n0 + row) * K + seg * 8;
            dstA[r] = sbase + SMEM_A_OFF + row * ROW_B + seg * 16;
            dstB[r] = sbase + SMEM_B_OFF + row * ROW_B + seg * 16;
        }

        float acc[4][4][4];
        #pragma unroll
        for (int mt = 0; mt < 4; mt++)
            #pragma unroll
            for (int nt = 0; nt < 4; nt++)
                #pragma unroll
                for (int i = 0; i < 4; i++) acc[mt][nt][i] = 0.f;

        auto stage = [&](int s) {
            int slot = s - (s / 3) * 3;
            int a_k0;
            if (ntpko) {
                int ki = s_kmap[s >> cin_l2];
                a_k0 = (ki << (cin_l2 + 6)) + ((s & ((1 << cin_l2) - 1)) << 6);
            } else {
                a_k0 = s << 6;
            }
            int b_k0 = s << 6;
            #pragma unroll
            for (int r = 0; r < 4; r++)
                cpasync16(dstA[r] + slot * STAGE_BYTES, baseA[r] + a_k0);
            #pragma unroll
            for (int r = 0; r < 4; r++)
                cpasync16(dstB[r] + slot * STAGE_BYTES, baseB[r] + b_k0);
            asm volatile("cp.async.commit_group;\n");
        };

        stage(0);
        if (KT > 1) stage(1);

        const int arow = wm * 64 + (lane & 15);
        uint32_t aAddrBase = sbase + SMEM_A_OFF + arow * ROW_B + (lane >> 4) * 16;
        const int brow = wn * 32 + ((lane >> 3) & 1) * 8 + (lane & 7);
        uint32_t bAddrBase = sbase + SMEM_B_OFF + brow * ROW_B + (lane >> 4) * 16;

        int slot = 0;
        for (int c = 0; c < KT; c++) {
            if (c == KT - 1) asm volatile("cp.async.wait_group 0;\n");
            else             asm volatile("cp.async.wait_group 1;\n");
            __syncthreads();
            if (c + 2 < KT) stage(c + 2);
            uint32_t aS = aAddrBase + slot * STAGE_BYTES;
            uint32_t bS = bAddrBase + slot * STAGE_BYTES;
            slot = (slot == 2) ? 0 : slot + 1;
            #pragma unroll
            for (int ks = 0; ks < 4; ks++) {
                uint32_t a[4][4], b[4][2];
                #pragma unroll
                for (int mt = 0; mt < 4; mt++) {
                    asm volatile("ldmatrix.sync.aligned.m8n8.x4.shared.b16 {%0,%1,%2,%3},[%4];"
                        : "=r"(a[mt][0]), "=r"(a[mt][1]), "=r"(a[mt][2]), "=r"(a[mt][3])
                        : "r"(aS + mt * 16 * ROW_B + ks * 32));
                }
                #pragma unroll
                for (int nt2 = 0; nt2 < 2; nt2++) {
                    uint32_t r0, r1, r2, r3;
                    asm volatile("ldmatrix.sync.aligned.m8n8.x4.shared.b16 {%0,%1,%2,%3},[%4];"
                        : "=r"(r0), "=r"(r1), "=r"(r2), "=r"(r3)
                        : "r"(bS + nt2 * 16 * ROW_B + ks * 32));
                    b[nt2 * 2 + 0][0] = r0; b[nt2 * 2 + 0][1] = r2;
                    b[nt2 * 2 + 1][0] = r1; b[nt2 * 2 + 1][1] = r3;
                }
                #pragma unroll
                for (int mt = 0; mt < 4; mt++)
                    #pragma unroll
                    for (int nt = 0; nt < 4; nt++)
                        asm volatile("mma.sync.aligned.m16n8k16.row.col.f32.f16.f16.f32 "
                            "{%0,%1,%2,%3},{%4,%5,%6,%7},{%8,%9},{%0,%1,%2,%3};"
                            : "+f"(acc[mt][nt][0]), "+f"(acc[mt][nt][1]),
                              "+f"(acc[mt][nt][2]), "+f"(acc[mt][nt][3])
                            : "r"(a[mt][0]), "r"(a[mt][1]), "r"(a[mt][2]), "r"(a[mt][3]),
                              "r"(b[nt][0]), "r"(b[nt][1]));
            }
        }

        // ---- epilogue ----
        #pragma unroll
        for (int mt = 0; mt < 4; mt++) {
            int r0 = m0 + wm * 64 + mt * 16 + (lane >> 2);
            #pragma unroll
            for (int nt = 0; nt < 4; nt++) {
                int c0 = n0 + wn * 32 + nt * 8 + (lane & 3) * 2;
                #pragma unroll
                for (int hh = 0; hh < 2; hh++) {
                    int rr = r0 + hh * 8;
                    float v0 = acc[mt][nt][hh * 2 + 0];
                    float v1 = acc[mt][nt][hh * 2 + 1];
                    if (MODE == MODE_CONV) {
                        int c0i = c0 & comask, c1i = (c0 + 1) & comask;
                        v0 = v0 * scale[c0i] + shift[c0i];
                        v1 = v1 * scale[c1i] + shift[c1i];
                        v0 = v0 > 0.f ? v0 : 0.1f * v0;
                        v1 = v1 > 0.f ? v1 : 0.1f * v1;
                    } else {
                        v0 += shift[c0];
                        v1 += shift[c0 + 1];
                        if (MODE == MODE_BIAS_RELU) { v0 = fmaxf(v0, 0.f); v1 = fmaxf(v1, 0.f); }
                    }
                    *(__half2*)(Cout + (size_t)rr * N_ + c0) = __floats2half2_rn(v0, v1);
                }
            }
        }
    }
}

// ---------------- scatter-add + im2col for conv1d ----------------
__global__ void buildbehavior_kernel(const int* __restrict__ person_idx) {
    int p = blockIdx.x / BB, b = blockIdx.x % BB;
    __shared__ int pid[NN];
    if (threadIdx.x < NN) pid[threadIdx.x] = person_idx[b * NN + threadIdx.x];
    __syncthreads();
    const __half* rowG = g_out2h + (size_t)b * N2;
    size_t base = (size_t)(p * BB + b) * K1D;
    for (int c = threadIdx.x; c < CD; c += blockDim.x) {
        int col = (c % 9) * C2 + (c / 9);
        float v = __half2float(rowG[col]);
        #pragma unroll
        for (int n = 0; n < NN; n++)
            if (pid[n] == p)
                v += __half2float(g_out2h[(size_t)(BB + b * NN + n) * N2 + col]);
        __half hv = __float2half(v);
        if (b + 1 < BB) g_A1d[(size_t)(p * BB + b + 1) * K1D + c] = hv;     // t=0
        g_A1d[base + CD + c] = hv;                                          // t=1
        if (b > 0) g_A1d[(size_t)(p * BB + b - 1) * K1D + 2 * CD + c] = hv; // t=2
        if (b == 0)      g_A1d[base + c] = __float2half(0.f);
        if (b == BB - 1) g_A1d[base + 2 * CD + c] = __float2half(0.f);
    }
}

// ---------------- fc2 ----------------
__global__ void fc2_kernel(const float* __restrict__ w, const float* __restrict__ bias,
                           float* __restrict__ out) {
    __shared__ float red[4][32];
    int r = blockIdx.x;
    int t = threadIdx.x;
    int n = t & 31, kg = t >> 5;
    float acc = 0.f;
    if (n < NBCLS) {
        const __half* hr = g_hh + (size_t)r * FC1DIM + kg * 256;
        for (int j = 0; j < 256; j++)
            acc = fmaf(__half2float(hr[j]), w[(size_t)(kg * 256 + j) * NBCLS + n], acc);
    }
    red[kg][n] = acc;
    __syncthreads();
    if (kg == 0 && n < NBCLS)
        out[(size_t)r * NBCLS + n] = red[0][n] + red[1][n] + red[2][n] + red[3][n] + bias[n];
}

// ---------------- launch ----------------
extern "C" void kernel_launch(void* const* d_in, const int* in_sizes, int n_in,
                              void* d_out, int out_size) {
    const float* fmap      = (const float*)d_in[0];
    const float* boxes     = (const float*)d_in[1];
    const int*   person_idx= (const int*)  d_in[2];
    const float* conv1_w   = (const float*)d_in[3];
    const float* bn1_g     = (const float*)d_in[4];
    const float* bn1_b     = (const float*)d_in[5];
    const float* bn1_m     = (const float*)d_in[6];
    const float* bn1_v     = (const float*)d_in[7];
    const float* conv2_w   = (const float*)d_in[8];
    const float* bn2_g     = (const float*)d_in[9];
    const float* bn2_b     = (const float*)d_in[10];
    const float* bn2_m     = (const float*)d_in[11];
    const float* bn2_v     = (const float*)d_in[12];
    const float* conv1d_w  = (const float*)d_in[13];
    const float* conv1d_b  = (const float*)d_in[14];
    const float* fc1_w     = (const float*)d_in[15];
    const float* fc1_b     = (const float*)d_in[16];
    const float* fc2_w     = (const float*)d_in[17];
    const float* fc2_b     = (const float*)d_in[18];
    float* out = (float*)d_out;

    void *p_roiH, *p_BT1, *p_out1, *p_BT2, *p_out2, *p_A1d, *p_BT1d,
         *p_feats, *p_BTf1, *p_hh, *p_sc1, *p_sh1, *p_sc2, *p_sh2, *p_rowmap;
    cudaGetSymbolAddress(&p_roiH, g_roiH);
    cudaGetSymbolAddress(&p_BT1,  g_BT1);
    cudaGetSymbolAddress(&p_out1, g_out1h);
    cudaGetSymbolAddress(&p_BT2,  g_BT2);
    cudaGetSymbolAddress(&p_out2, g_out2h);
    cudaGetSymbolAddress(&p_A1d,  g_A1d);
    cudaGetSymbolAddress(&p_BT1d, g_BT1d);
    cudaGetSymbolAddress(&p_feats, g_feats);
    cudaGetSymbolAddress(&p_BTf1, g_BTf1);
    cudaGetSymbolAddress(&p_hh,   g_hh);
    cudaGetSymbolAddress(&p_sc1,  g_scale1);
    cudaGetSymbolAddress(&p_sh1,  g_shift1);
    cudaGetSymbolAddress(&p_sc2,  g_scale2);
    cudaGetSymbolAddress(&p_sh2,  g_shift2);
    cudaGetSymbolAddress(&p_rowmap, g_rowmap);

    static bool inited = false;
    static cudaStream_t s1, s2;
    static cudaEvent_t evFork, evW1, evW2;
    if (!inited) {
        inited = true;
        cudaStreamCreateWithFlags(&s1, cudaStreamNonBlocking);
        cudaStreamCreateWithFlags(&s2, cudaStreamNonBlocking);
        cudaEventCreateWithFlags(&evFork, cudaEventDisableTiming);
        cudaEventCreateWithFlags(&evW1, cudaEventDisableTiming);
        cudaEventCreateWithFlags(&evW2, cudaEventDisableTiming);
        cudaFuncSetAttribute(gemm_f16<MODE_CONV>,
                             cudaFuncAttributeMaxDynamicSharedMemorySize, SMEM_TOTAL);
        cudaFuncSetAttribute(gemm_f16<MODE_BIAS>,
                             cudaFuncAttributeMaxDynamicSharedMemorySize, SMEM_TOTAL);
        cudaFuncSetAttribute(gemm_f16<MODE_BIAS_RELU>,
                             cudaFuncAttributeMaxDynamicSharedMemorySize, SMEM_TOTAL);
    }

    // ---- fork: weight prep on side streams ----
    bnfold_kernel<<<3, 256>>>(bn1_g, bn1_b, bn1_m, bn1_v, bn2_g, bn2_b, bn2_m, bn2_v);
    cudaEventRecord(evFork, 0);
    cudaStreamWaitEvent(s1, evFork, 0);
    cudaStreamWaitEvent(s2, evFork, 0);

    expand_conv_w<CC, C1><<<N1, 256, 0, s1>>>(conv1_w, (__half*)p_BT1);
    cudaEventRecord(evW1, s1);

    expand_conv_w<C1, C2><<<N2, 256, 0, s2>>>(conv2_w, (__half*)p_BT2);
    tw1d_kernel<<<CD, 256, 0, s2>>>(conv1d_w);
    twfc1_kernel<<<FC1DIM, 256, 0, s2>>>(fc1_w);
    rowmap_kernel<<<4, 256, 0, s2>>>(person_idx);
    cudaEventRecord(evW2, s2);

    // ---- main branch: fmap transpose -> roi align ----
    tfmap_kernel<<<dim3(7, 32, 64), dim3(32, 8)>>>(fmap);
    roialign_kernel<<<S_TOT, 256>>>(boxes);

    // ---- join W1, conv1: 324 tiles on 296 persistent slots ----
    cudaStreamWaitEvent(0, evW1, 0);
    {
        int ntiles = (N1 / 128) * (S_PAD / 128);   // 324
        int grid = ntiles < GMAX ? ntiles : GMAX;  // 296
        gemm_f16<MODE_CONV><<<grid, 256, SMEM_TOTAL>>>(
            (const __half*)p_roiH, (const __half*)p_BT1, (__half*)p_out1,
            N1, K1, (const float*)p_sc1, (const float*)p_sh1, C1 - 1,
            ntiles, /*nby=*/S_PAD / 128, /*ntpko=*/C1 / 128, /*cin_l2=*/4, nullptr);
    }

    // ---- join W2, conv2: 162 tiles ----
    cudaStreamWaitEvent(0, evW2, 0);
    {
        int ntiles = (N2 / 128) * (S_PAD / 128);   // 162
        gemm_f16<MODE_CONV><<<ntiles, 256, SMEM_TOTAL>>>(
            (const __half*)p_out1, (const __half*)p_BT2, (__half*)p_out2,
            N2, K2, (const float*)p_sc2, (const float*)p_sh2, C2 - 1,
            ntiles, /*nby=*/S_PAD / 128, /*ntpko=*/C2 / 128, /*cin_l2=*/3, nullptr);
    }

    // ---- scatter-add + im2col ----
    buildbehavior_kernel<<<PP * BB, 256>>>(person_idx);

    // ---- conv1d: M=1024 gathered rows, N=2304, K=6912 -> writes g_feats ----
    {
        int ntiles = (CD / 128) * ((BB * NN) / 128);   // 144
        gemm_f16<MODE_BIAS><<<ntiles, 256, SMEM_TOTAL>>>(
            (const __half*)p_A1d, (const __half*)p_BT1d, (__half*)p_feats,
            CD, K1D, nullptr, conv1d_b, 0,
            ntiles, /*nbx=*/CD / 128, 0, 0, (const int*)p_rowmap);
    }

    // ---- fc1: M=1024, N=1024, K=2304 ----
    {
        int ntiles = (FC1DIM / 128) * ((BB * NN) / 128);   // 64
        gemm_f16<MODE_BIAS_RELU><<<ntiles, 256, SMEM_TOTAL>>>(
            (const __half*)p_feats, (const __half*)p_BTf1, (__half*)p_hh,
            FC1DIM, CD, nullptr, fc1_b, 0,
            ntiles, /*nbx=*/FC1DIM / 128, 0, 0, nullptr);
    }

    // ---- fc2 -> output ----
    fc2_kernel<<<BB * NN, 128>>>(fc2_w, fc2_b, out);
}

// round 13
// speedup vs baseline: 7.8452x; 1.0850x over previous
#include <cuda_runtime.h>
#include <cuda_fp16.h>
#include <cstdint>

// ---------------- problem constants ----------------
#define BB 64
#define NN 16
#define PP 20
#define NBCLS 30
#define CC 1024
#define FF 14
#define SPAT 196
#define S_TOT 1088
#define S_PAD 1152
#define C1 512
#define C2 256
#define CD 2304
#define K1 (9*CC)           // 9216
#define N1 (9*C1)           // 4608
#define K2 (9*C1)           // 4608
#define N2 (9*C2)           // 2304
#define K1D (3*CD)          // 6912
#define M1D (PP*BB)         // 1280
#define FC1DIM 1024
#define GMAX 296            // 148 SMs x 2 CTA

// ---------------- static device scratch ----------------
__device__ __half g_roiH[(size_t)S_PAD*K1];
__device__ __half g_BT1[(size_t)N1*K1];
__device__ __half g_out1h[(size_t)S_PAD*N1];
__device__ __half g_BT2[(size_t)N2*K2];
__device__ __half g_out2h[(size_t)S_PAD*N2];
__device__ __half g_A1d[(size_t)M1D*K1D];
__device__ __half g_BT1d[(size_t)CD*K1D];
__device__ __half g_feats[(size_t)BB*NN*CD];
__device__ __half g_BTf1[(size_t)FC1DIM*CD];
__device__ __half g_hh[(size_t)BB*NN*FC1DIM];
__device__ float  g_scale1[C1], g_shift1[C1];
__device__ float  g_scale2[C2], g_shift2[C2];
__device__ int    g_rowmap[BB*NN];

// ko order by descending valid-tap count: center(9), edges(6), corners(4)
__constant__ int c_korder[9] = {4, 1, 3, 5, 7, 0, 2, 6, 8};

// ---------------- BN folding ----------------
__global__ void bnfold_kernel(const float* g1, const float* b1, const float* m1, const float* v1,
                              const float* g2, const float* b2, const float* m2, const float* v2) {
    int t = blockIdx.x * blockDim.x + threadIdx.x;
    if (t < C1) {
        float s = g1[t] * rsqrtf(v1[t] + 1e-5f);
        g_scale1[t] = s;
        g_shift1[t] = b1[t] - m1[t] * s;
    } else if (t < C1 + C2) {
        int i = t - C1;
        float s = g2[i] * rsqrtf(v2[i] + 1e-5f);
        g_scale2[i] = s;
        g_shift2[i] = b2[i] - m2[i] * s;
    }
}

// ---------------- packed expanded conv weights ----------------
template<int CIN, int COUT>
__global__ void expand_conv_w(const float* __restrict__ w, __half* __restrict__ BT) {
    int n = blockIdx.x;
    int co = n & (COUT - 1), ko = n / COUT;
    int oy = ko / 3, ox = ko % 3;
    int taps[9]; int nv = 0;
    #pragma unroll
    for (int kiy = 0; kiy < 3; kiy++)
        #pragma unroll
        for (int kix = 0; kix < 3; kix++) {
            int ky = kiy - oy + 1, kx = kix - ox + 1;
            if ((unsigned)ky < 3u && (unsigned)kx < 3u) taps[nv++] = ky * 3 + kx;
        }
    const int Kp = nv * CIN;
    for (int k = threadIdx.x; k < Kp; k += blockDim.x) {
        int kidx = k / CIN, ci = k & (CIN - 1);
        BT[(size_t)n * (9 * CIN) + k] = __float2half(w[((size_t)co * CIN + ci) * 9 + taps[kidx]]);
    }
}

// conv1d weights: BT[co][t*CD+ci] = w[co][ci][t]
__global__ void tw1d_kernel(const float* __restrict__ w) {
    int co = blockIdx.x;
    for (int ci = threadIdx.x; ci < CD; ci += blockDim.x) {
        #pragma unroll
        for (int t = 0; t < 3; t++)
            g_BT1d[(size_t)co * K1D + t * CD + ci] = __float2half(w[((size_t)co * CD + ci) * 3 + t]);
    }
}

// fc1 weights: BT[n][k] = w[k][n]
__global__ void twfc1_kernel(const float* __restrict__ w) {
    int n = blockIdx.x;
    for (int k = threadIdx.x; k < CD; k += blockDim.x)
        g_BTf1[(size_t)n * CD + k] = __float2half(w[(size_t)k * FC1DIM + n]);
}

// rowmap: output row r of conv1d = behavior row (pid[r]*64 + b)
__global__ void rowmap_kernel(const int* __restrict__ person_idx) {
    int r = blockIdx.x * blockDim.x + threadIdx.x;
    if (r < BB * NN)
        g_rowmap[r] = person_idx[r] * BB + (r >> 4);
}

// ---------------- fused fmap-stage + roi align -> fp16 A of conv1 ----------------
// block = (c-chunk of 128, b). Stages fmap[b][chunk][:] into smem once
// (row stride 129 floats: conflict-free for both yx-major fill and c-major reads),
// then computes all 17 rois x 9 outputs for those channels.
#define ROI_CCHUNK 128
#define ROI_TSTRIDE 129
#define ROI_SMEM (SPAT * ROI_TSTRIDE * 4)   // 101136

__global__ void __launch_bounds__(256) roifused_kernel(
    const float* __restrict__ fmap, const float* __restrict__ boxes)
{
    extern __shared__ float tile[];          // [196][129]
    int b = blockIdx.y;
    int c0 = blockIdx.x * ROI_CCHUNK;
    int tid = threadIdx.x;

    const float* src = fmap + ((size_t)b * CC + c0) * SPAT;
    for (int i = tid; i < ROI_CCHUNK * SPAT; i += 256) {
        int c = i / SPAT, yx = i - c * SPAT;
        tile[yx * ROI_TSTRIDE + c] = src[(size_t)c * SPAT + yx];
    }
    __syncthreads();

    int c = tid & 127;
    int rg = tid >> 7;                       // 0 or 1: interleave rois
    for (int rr = rg; rr < NN + 1; rr += 2) {
        int s = (rr == 0) ? b : (BB + b * NN + (rr - 1));
        float x1, y1, x2, y2;
        if (rr == 0) { x1 = 0.f; y1 = 0.f; x2 = (float)FF; y2 = (float)FF; }
        else {
            const float* bx = boxes + (size_t)(b * NN + rr - 1) * 4;
            x1 = bx[0]; y1 = bx[1]; x2 = bx[2]; y2 = bx[3];
        }
        float rw = fmaxf(x2 - x1, 1.f), rh = fmaxf(y2 - y1, 1.f);
        float scy = rh / 3.0f, scx = rw / 3.0f;
        float wyv[6], wxv[6];
        int y0v[6], y1v[6], x0v[6], x1v[6];
        #pragma unroll
        for (int i = 0; i < 6; i++) {
            float pos = ((float)i + 0.5f) * 0.5f;
            float ys = fminf(fmaxf(y1 + pos * scy, 0.f), 13.f);
            float xs = fminf(fmaxf(x1 + pos * scx, 0.f), 13.f);
            float y0 = floorf(ys), x0 = floorf(xs);
            y0v[i] = (int)y0; x0v[i] = (int)x0;
            y1v[i] = min(y0v[i] + 1, 13); x1v[i] = min(x0v[i] + 1, 13);
            wyv[i] = ys - y0; wxv[i] = xs - x0;
        }
        float acc[9];
        #pragma unroll
        for (int k = 0; k < 9; k++) acc[k] = 0.f;
        #pragma unroll
        for (int sy = 0; sy < 6; sy++) {
            float wy = wyv[sy];
            int y0 = y0v[sy], y1 = y1v[sy];
            #pragma unroll
            for (int sx = 0; sx < 6; sx++) {
                float wx = wxv[sx];
                int x0 = x0v[sx], x1 = x1v[sx];
                float v00 = tile[(y0 * FF + x0) * ROI_TSTRIDE + c];
                float v01 = tile[(y0 * FF + x1) * ROI_TSTRIDE + c];
                float v10 = tile[(y1 * FF + x0) * ROI_TSTRIDE + c];
                float v11 = tile[(y1 * FF + x1) * ROI_TSTRIDE + c];
                float v = v00 * (1.f - wy) * (1.f - wx) + v01 * (1.f - wy) * wx
                        + v10 * wy * (1.f - wx) + v11 * wy * wx;
                acc[(sy >> 1) * 3 + (sx >> 1)] += v;
            }
        }
        #pragma unroll
        for (int k = 0; k < 9; k++)
            g_roiH[((size_t)s * 9 + k) * CC + c0 + c] = __float2half(acc[k] * 0.25f);
    }
}

// ---------------- fp16 tensor-core GEMM (mma.sync), persistent LPT tiles ----------------
#define MODE_CONV      0
#define MODE_BIAS      1
#define MODE_BIAS_RELU 2

#define ROW_B  144
#define STAGE_BYTES (128 * ROW_B)   // 18432
#define SMEM_A_OFF  0
#define SMEM_B_OFF  (3 * STAGE_BYTES)
#define SMEM_TOTAL  (6 * STAGE_BYTES)   // 110592

__device__ __forceinline__ void cpasync16(uint32_t dst, const void* src) {
    asm volatile("cp.async.cg.shared.global [%0], [%1], 16;\n" :: "r"(dst), "l"(src));
}

template<int MODE>
__global__ void __launch_bounds__(256, 2) gemm_f16(
    const __half* __restrict__ A, const __half* __restrict__ BT,
    __half* __restrict__ Cout, int N_, int K,
    const float* __restrict__ scale, const float* __restrict__ shift, int comask,
    int ntiles, int nbx, int ntpko, int cin_l2, const int* __restrict__ rowmap)
{
    extern __shared__ char smem[];
    __shared__ int s_kmap[10];
    uint32_t sbase;
    asm("{ .reg .u64 t; cvta.to.shared.u64 t, %1; cvt.u32.u64 %0, t; }" : "=r"(sbase) : "l"(smem));
    const int tid = threadIdx.x, lane = tid & 31, wid = tid >> 5;
    const int wm = wid >> 2, wn = wid & 3;
    const int G = gridDim.x;

    for (int which = 0; which < 2; which++) {
        int u;
        if (which == 0) {
            u = blockIdx.x;
        } else {
            u = 2 * G - 1 - blockIdx.x;
            if (u < G || u >= ntiles) break;
        }

        int m0, n0;
        __syncthreads();
        if (ntpko) {
            int gsz = ntpko * nbx;
            int g = u / gsz;
            int rem = u - g * gsz;
            int ko = c_korder[g];
            int by = rem / ntpko;
            int nx = rem - by * ntpko;
            m0 = by << 7;
            n0 = (ko * ntpko + nx) << 7;
            if (tid == 0) {
                int oy = ko / 3, ox = ko % 3;
                int nv = 0;
                #pragma unroll
                for (int kiy = 0; kiy < 3; kiy++)
                    #pragma unroll
                    for (int kix = 0; kix < 3; kix++) {
                        int ky = kiy - oy + 1, kx = kix - ox + 1;
                        if ((unsigned)ky < 3u && (unsigned)kx < 3u)
                            s_kmap[nv++] = kiy * 3 + kix;
                    }
                s_kmap[9] = nv << cin_l2;
            }
        } else {
            int by = u / nbx;
            m0 = by << 7;
            n0 = (u - by * nbx) << 7;
            if (tid == 0) s_kmap[9] = K >> 6;
        }
        __syncthreads();
        const int KT = s_kmap[9];

        const __half* baseA[4];
        const __half* baseB[4];
        uint32_t dstA[4], dstB[4];
        #pragma unroll
        for (int r = 0; r < 4; r++) {
            int q = tid + r * 256;
            int row = q >> 3, seg = q & 7;
            int gr = m0 + row;
            if (rowmap) gr = rowmap[gr];
            baseA[r] = A + (size_t)gr * K + seg * 8;
            baseB[r] = BT + (size_t)(n0 + row) * K + seg * 8;
            dstA[r] = sbase + SMEM_A_OFF + row * ROW_B + seg * 16;
            dstB[r] = sbase + SMEM_B_OFF + row * ROW_B + seg * 16;
        }

        float acc[4][4][4];
        #pragma unroll
        for (int mt = 0; mt < 4; mt++)
            #pragma unroll
            for (int nt = 0; nt < 4; nt++)
                #pragma unroll
                for (int i = 0; i < 4; i++) acc[mt][nt][i] = 0.f;

        auto stage = [&](int s) {
            int slot = s - (s / 3) * 3;
            int a_k0;
            if (ntpko) {
                int ki = s_kmap[s >> cin_l2];
                a_k0 = (ki << (cin_l2 + 6)) + ((s & ((1 << cin_l2) - 1)) << 6);
            } else {
                a_k0 = s << 6;
            }
            int b_k0 = s << 6;
            #pragma unroll
            for (int r = 0; r < 4; r++)
                cpasync16(dstA[r] + slot * STAGE_BYTES, baseA[r] + a_k0);
            #pragma unroll
            for (int r = 0; r < 4; r++)
                cpasync16(dstB[r] + slot * STAGE_BYTES, baseB[r] + b_k0);
            asm volatile("cp.async.commit_group;\n");
        };

        stage(0);
        if (KT > 1) stage(1);

        const int arow = wm * 64 + (lane & 15);
        uint32_t aAddrBase = sbase + SMEM_A_OFF + arow * ROW_B + (lane >> 4) * 16;
        const int brow = wn * 32 + ((lane >> 3) & 1) * 8 + (lane & 7);
        uint32_t bAddrBase = sbase + SMEM_B_OFF + brow * ROW_B + (lane >> 4) * 16;

        int slot = 0;
        for (int c = 0; c < KT; c++) {
            if (c == KT - 1) asm volatile("cp.async.wait_group 0;\n");
            else             asm volatile("cp.async.wait_group 1;\n");
            __syncthreads();
            if (c + 2 < KT) stage(c + 2);
            uint32_t aS = aAddrBase + slot * STAGE_BYTES;
            uint32_t bS = bAddrBase + slot * STAGE_BYTES;
            slot = (slot == 2) ? 0 : slot + 1;
            #pragma unroll
            for (int ks = 0; ks < 4; ks++) {
                uint32_t a[4][4], b[4][2];
                #pragma unroll
                for (int mt = 0; mt < 4; mt++) {
                    asm volatile("ldmatrix.sync.aligned.m8n8.x4.shared.b16 {%0,%1,%2,%3},[%4];"
                        : "=r"(a[mt][0]), "=r"(a[mt][1]), "=r"(a[mt][2]), "=r"(a[mt][3])
                        : "r"(aS + mt * 16 * ROW_B + ks * 32));
                }
                #pragma unroll
                for (int nt2 = 0; nt2 < 2; nt2++) {
                    uint32_t r0, r1, r2, r3;
                    asm volatile("ldmatrix.sync.aligned.m8n8.x4.shared.b16 {%0,%1,%2,%3},[%4];"
                        : "=r"(r0), "=r"(r1), "=r"(r2), "=r"(r3)
                        : "r"(bS + nt2 * 16 * ROW_B + ks * 32));
                    b[nt2 * 2 + 0][0] = r0; b[nt2 * 2 + 0][1] = r2;
                    b[nt2 * 2 + 1][0] = r1; b[nt2 * 2 + 1][1] = r3;
                }
                #pragma unroll
                for (int mt = 0; mt < 4; mt++)
                    #pragma unroll
                    for (int nt = 0; nt < 4; nt++)
                        asm volatile("mma.sync.aligned.m16n8k16.row.col.f32.f16.f16.f32 "
                            "{%0,%1,%2,%3},{%4,%5,%6,%7},{%8,%9},{%0,%1,%2,%3};"
                            : "+f"(acc[mt][nt][0]), "+f"(acc[mt][nt][1]),
                              "+f"(acc[mt][nt][2]), "+f"(acc[mt][nt][3])
                            : "r"(a[mt][0]), "r"(a[mt][1]), "r"(a[mt][2]), "r"(a[mt][3]),
                              "r"(b[nt][0]), "r"(b[nt][1]));
            }
        }

        #pragma unroll
        for (int mt = 0; mt < 4; mt++) {
            int r0 = m0 + wm * 64 + mt * 16 + (lane >> 2);
            #pragma unroll
            for (int nt = 0; nt < 4; nt++) {
                int c0 = n0 + wn * 32 + nt * 8 + (lane & 3) * 2;
                #pragma unroll
                for (int hh = 0; hh < 2; hh++) {
                    int rr = r0 + hh * 8;
                    float v0 = acc[mt][nt][hh * 2 + 0];
                    float v1 = acc[mt][nt][hh * 2 + 1];
                    if (MODE == MODE_CONV) {
                        int c0i = c0 & comask, c1i = (c0 + 1) & comask;
                        v0 = v0 * scale[c0i] + shift[c0i];
                        v1 = v1 * scale[c1i] + shift[c1i];
                        v0 = v0 > 0.f ? v0 : 0.1f * v0;
                        v1 = v1 > 0.f ? v1 : 0.1f * v1;
                    } else {
                        v0 += shift[c0];
                        v1 += shift[c0 + 1];
                        if (MODE == MODE_BIAS_RELU) { v0 = fmaxf(v0, 0.f); v1 = fmaxf(v1, 0.f); }
                    }
                    *(__half2*)(Cout + (size_t)rr * N_ + c0) = __floats2half2_rn(v0, v1);
                }
            }
        }
    }
}

// ---------------- scatter-add + im2col for conv1d (smem-staged) ----------------
// block = (pgroup of 5, b). 17 conv2 rows staged to smem once; per c the 16
// addends are loaded once into registers and combined per-p.
#define BB_SMEM (17 * N2 * 2)   // 78336

__global__ void __launch_bounds__(256) buildbehavior_kernel(const int* __restrict__ person_idx) {
    extern __shared__ __half srows[];        // [17][N2]
    __shared__ int pid[NN];
    int b = blockIdx.y;
    int p0 = blockIdx.x * 5;
    int tid = threadIdx.x;
    if (tid < NN) pid[tid] = person_idx[b * NN + tid];

    const int row4 = N2 / 8;                 // float4s per row
    for (int i = tid; i < 17 * row4; i += 256) {
        int rr = i / row4, off = i - rr * row4;
        int gr = (rr == 0) ? b : (BB + b * NN + rr - 1);
        ((float4*)srows)[i] = ((const float4*)(g_out2h + (size_t)gr * N2))[off];
    }
    __syncthreads();

    for (int c = tid; c < CD; c += 256) {
        int col = (c % 9) * C2 + (c / 9);
        float g = __half2float(srows[col]);
        float v[NN];
        #pragma unroll
        for (int n = 0; n < NN; n++)
            v[n] = __half2float(srows[(1 + n) * N2 + col]);
        #pragma unroll
        for (int pi = 0; pi < 5; pi++) {
            int p = p0 + pi;
            float s = g;
            #pragma unroll
            for (int n = 0; n < NN; n++)
                if (pid[n] == p) s += v[n];
            __half hv = __float2half(s);
            size_t base = (size_t)(p * BB + b) * K1D;
            if (b + 1 < BB) g_A1d[(size_t)(p * BB + b + 1) * K1D + c] = hv;     // t=0
            g_A1d[base + CD + c] = hv;                                          // t=1
            if (b > 0) g_A1d[(size_t)(p * BB + b - 1) * K1D + 2 * CD + c] = hv; // t=2
            if (b == 0)      g_A1d[base + c] = __float2half(0.f);
            if (b == BB - 1) g_A1d[base + 2 * CD + c] = __float2half(0.f);
        }
    }
}

// ---------------- fc2 ----------------
__global__ void fc2_kernel(const float* __restrict__ w, const float* __restrict__ bias,
                           float* __restrict__ out) {
    __shared__ float red[4][32];
    int r = blockIdx.x;
    int t = threadIdx.x;
    int n = t & 31, kg = t >> 5;
    float acc = 0.f;
    if (n < NBCLS) {
        const __half* hr = g_hh + (size_t)r * FC1DIM + kg * 256;
        for (int j = 0; j < 256; j++)
            acc = fmaf(__half2float(hr[j]), w[(size_t)(kg * 256 + j) * NBCLS + n], acc);
    }
    red[kg][n] = acc;
    __syncthreads();
    if (kg == 0 && n < NBCLS)
        out[(size_t)r * NBCLS + n] = red[0][n] + red[1][n] + red[2][n] + red[3][n] + bias[n];
}

// ---------------- launch ----------------
extern "C" void kernel_launch(void* const* d_in, const int* in_sizes, int n_in,
                              void* d_out, int out_size) {
    const float* fmap      = (const float*)d_in[0];
    const float* boxes     = (const float*)d_in[1];
    const int*   person_idx= (const int*)  d_in[2];
    const float* conv1_w   = (const float*)d_in[3];
    const float* bn1_g     = (const float*)d_in[4];
    const float* bn1_b     = (const float*)d_in[5];
    const float* bn1_m     = (const float*)d_in[6];
    const float* bn1_v     = (const float*)d_in[7];
    const float* conv2_w   = (const float*)d_in[8];
    const float* bn2_g     = (const float*)d_in[9];
    const float* bn2_b     = (const float*)d_in[10];
    const float* bn2_m     = (const float*)d_in[11];
    const float* bn2_v     = (const float*)d_in[12];
    const float* conv1d_w  = (const float*)d_in[13];
    const float* conv1d_b  = (const float*)d_in[14];
    const float* fc1_w     = (const float*)d_in[15];
    const float* fc1_b     = (const float*)d_in[16];
    const float* fc2_w     = (const float*)d_in[17];
    const float* fc2_b     = (const float*)d_in[18];
    float* out = (float*)d_out;

    void *p_roiH, *p_BT1, *p_out1, *p_BT2, *p_out2, *p_A1d, *p_BT1d,
         *p_feats, *p_BTf1, *p_hh, *p_sc1, *p_sh1, *p_sc2, *p_sh2, *p_rowmap;
    cudaGetSymbolAddress(&p_roiH, g_roiH);
    cudaGetSymbolAddress(&p_BT1,  g_BT1);
    cudaGetSymbolAddress(&p_out1, g_out1h);
    cudaGetSymbolAddress(&p_BT2,  g_BT2);
    cudaGetSymbolAddress(&p_out2, g_out2h);
    cudaGetSymbolAddress(&p_A1d,  g_A1d);
    cudaGetSymbolAddress(&p_BT1d, g_BT1d);
    cudaGetSymbolAddress(&p_feats, g_feats);
    cudaGetSymbolAddress(&p_BTf1, g_BTf1);
    cudaGetSymbolAddress(&p_hh,   g_hh);
    cudaGetSymbolAddress(&p_sc1,  g_scale1);
    cudaGetSymbolAddress(&p_sh1,  g_shift1);
    cudaGetSymbolAddress(&p_sc2,  g_scale2);
    cudaGetSymbolAddress(&p_sh2,  g_shift2);
    cudaGetSymbolAddress(&p_rowmap, g_rowmap);

    static bool inited = false;
    static cudaStream_t s1, s2;
    static cudaEvent_t evFork, evW1, evW2;
    if (!inited) {
        inited = true;
        cudaStreamCreateWithFlags(&s1, cudaStreamNonBlocking);
        cudaStreamCreateWithFlags(&s2, cudaStreamNonBlocking);
        cudaEventCreateWithFlags(&evFork, cudaEventDisableTiming);
        cudaEventCreateWithFlags(&evW1, cudaEventDisableTiming);
        cudaEventCreateWithFlags(&evW2, cudaEventDisableTiming);
        cudaFuncSetAttribute(gemm_f16<MODE_CONV>,
                             cudaFuncAttributeMaxDynamicSharedMemorySize, SMEM_TOTAL);
        cudaFuncSetAttribute(gemm_f16<MODE_BIAS>,
                             cudaFuncAttributeMaxDynamicSharedMemorySize, SMEM_TOTAL);
        cudaFuncSetAttribute(gemm_f16<MODE_BIAS_RELU>,
                             cudaFuncAttributeMaxDynamicSharedMemorySize, SMEM_TOTAL);
        cudaFuncSetAttribute(roifused_kernel,
                             cudaFuncAttributeMaxDynamicSharedMemorySize, ROI_SMEM);
        cudaFuncSetAttribute(buildbehavior_kernel,
                             cudaFuncAttributeMaxDynamicSharedMemorySize, BB_SMEM);
    }

    // ---- fork: weight prep on side streams ----
    bnfold_kernel<<<3, 256>>>(bn1_g, bn1_b, bn1_m, bn1_v, bn2_g, bn2_b, bn2_m, bn2_v);
    cudaEventRecord(evFork, 0);
    cudaStreamWaitEvent(s1, evFork, 0);
    cudaStreamWaitEvent(s2, evFork, 0);

    expand_conv_w<CC, C1><<<N1, 256, 0, s1>>>(conv1_w, (__half*)p_BT1);
    cudaEventRecord(evW1, s1);

    expand_conv_w<C1, C2><<<N2, 256, 0, s2>>>(conv2_w, (__half*)p_BT2);
    tw1d_kernel<<<CD, 256, 0, s2>>>(conv1d_w);
    twfc1_kernel<<<FC1DIM, 256, 0, s2>>>(fc1_w);
    rowmap_kernel<<<4, 256, 0, s2>>>(person_idx);
    cudaEventRecord(evW2, s2);

    // ---- main branch: fused fmap-stage + roi align ----
    roifused_kernel<<<dim3(CC / ROI_CCHUNK, BB), 256, ROI_SMEM>>>(fmap, boxes);

    // ---- join W1, conv1: 324 tiles on 296 persistent slots ----
    cudaStreamWaitEvent(0, evW1, 0);
    {
        int ntiles = (N1 / 128) * (S_PAD / 128);   // 324
        int grid = ntiles < GMAX ? ntiles : GMAX;  // 296
        gemm_f16<MODE_CONV><<<grid, 256, SMEM_TOTAL>>>(
            (const __half*)p_roiH, (const __half*)p_BT1, (__half*)p_out1,
            N1, K1, (const float*)p_sc1, (const float*)p_sh1, C1 - 1,
            ntiles, /*nby=*/S_PAD / 128, /*ntpko=*/C1 / 128, /*cin_l2=*/4, nullptr);
    }

    // ---- join W2, conv2: 162 tiles ----
    cudaStreamWaitEvent(0, evW2, 0);
    {
        int ntiles = (N2 / 128) * (S_PAD / 128);   // 162
        gemm_f16<MODE_CONV><<<ntiles, 256, SMEM_TOTAL>>>(
            (const __half*)p_out1, (const __half*)p_BT2, (__half*)p_out2,
            N2, K2, (const float*)p_sc2, (const float*)p_sh2, C2 - 1,
            ntiles, /*nby=*/S_PAD / 128, /*ntpko=*/C2 / 128, /*cin_l2=*/3, nullptr);
    }

    // ---- scatter-add + im2col (smem-staged) ----
    buildbehavior_kernel<<<dim3(PP / 5, BB), 256, BB_SMEM>>>(person_idx);

    // ---- conv1d: M=1024 gathered rows, N=2304, K=6912 -> writes g_feats ----
    {
        int ntiles = (CD / 128) * ((BB * NN) / 128);   // 144
        gemm_f16<MODE_BIAS><<<ntiles, 256, SMEM_TOTAL>>>(
            (const __half*)p_A1d, (const __half*)p_BT1d, (__half*)p_feats,
            CD, K1D, nullptr, conv1d_b, 0,
            ntiles, /*nbx=*/CD / 128, 0, 0, (const int*)p_rowmap);
    }

    // ---- fc1: M=1024, N=1024, K=2304 ----
    {
        int ntiles = (FC1DIM / 128) * ((BB * NN) / 128);   // 64
        gemm_f16<MODE_BIAS_RELU><<<ntiles, 256, SMEM_TOTAL>>>(
            (const __half*)p_feats, (const __half*)p_BTf1, (__half*)p_hh,
            FC1DIM, CD, nullptr, fc1_b, 0,
            ntiles, /*nbx=*/FC1DIM / 128, 0, 0, nullptr);
    }

    // ---- fc2 -> output ----
    fc2_kernel<<<BB * NN, 128>>>(fc2_w, fc2_b, out);
}

// round 15
// speedup vs baseline: 7.9103x; 1.0083x over previous
#include <cuda_runtime.h>
#include <cuda_fp16.h>
#include <cstdint>

// ---------------- problem constants ----------------
#define BB 64
#define NN 16
#define PP 20
#define NBCLS 30
#define CC 1024
#define FF 14
#define SPAT 196
#define S_TOT 1088
#define S_PAD 1152
#define C1 512
#define C2 256
#define CD 2304
#define K1 (9*CC)           // 9216
#define N1 (9*C1)           // 4608
#define K2 (9*C1)           // 4608
#define N2 (9*C2)           // 2304
#define K1D (3*CD)          // 6912
#define M1D (PP*BB)         // 1280
#define FC1DIM 1024
#define GMAX 296            // 148 SMs x 2 CTA

// ---------------- static device scratch ----------------
__device__ __half g_roiH[(size_t)S_PAD*K1];
__device__ __half g_BT1[(size_t)N1*K1];
__device__ __half g_out1h[(size_t)S_PAD*N1];
__device__ __half g_BT2[(size_t)N2*K2];
__device__ __half g_out2h[(size_t)S_PAD*N2];
__device__ __half g_A1d[(size_t)M1D*K1D];
__device__ __half g_BT1d[(size_t)CD*K1D];
__device__ __half g_feats[(size_t)BB*NN*CD];
__device__ __half g_BTf1[(size_t)FC1DIM*CD];
__device__ __half g_hh[(size_t)BB*NN*FC1DIM];
__device__ float  g_scale1[C1], g_shift1[C1];
__device__ float  g_scale2[C2], g_shift2[C2];
__device__ int    g_rowmap[BB*NN];

// ko order by descending valid-tap count: center(9), edges(6), corners(4)
__constant__ int c_korder[9] = {4, 1, 3, 5, 7, 0, 2, 6, 8};

// ---------------- BN folding ----------------
__global__ void bnfold_kernel(const float* g1, const float* b1, const float* m1, const float* v1,
                              const float* g2, const float* b2, const float* m2, const float* v2) {
    int t = blockIdx.x * blockDim.x + threadIdx.x;
    if (t < C1) {
        float s = g1[t] * rsqrtf(v1[t] + 1e-5f);
        g_scale1[t] = s;
        g_shift1[t] = b1[t] - m1[t] * s;
    } else if (t < C1 + C2) {
        int i = t - C1;
        float s = g2[i] * rsqrtf(v2[i] + 1e-5f);
        g_scale2[i] = s;
        g_shift2[i] = b2[i] - m2[i] * s;
    }
}

// ---------------- packed expanded conv weights ----------------
template<int CIN, int COUT>
__global__ void expand_conv_w(const float* __restrict__ w, __half* __restrict__ BT) {
    int n = blockIdx.x;
    int co = n & (COUT - 1), ko = n / COUT;
    int oy = ko / 3, ox = ko % 3;
    int taps[9]; int nv = 0;
    #pragma unroll
    for (int kiy = 0; kiy < 3; kiy++)
        #pragma unroll
        for (int kix = 0; kix < 3; kix++) {
            int ky = kiy - oy + 1, kx = kix - ox + 1;
            if ((unsigned)ky < 3u && (unsigned)kx < 3u) taps[nv++] = ky * 3 + kx;
        }
    const int Kp = nv * CIN;
    for (int k = threadIdx.x; k < Kp; k += blockDim.x) {
        int kidx = k / CIN, ci = k & (CIN - 1);
        BT[(size_t)n * (9 * CIN) + k] = __float2half(w[((size_t)co * CIN + ci) * 9 + taps[kidx]]);
    }
}

// ---------------- merged small prep: conv1d weights + fc1 weights + rowmap ----------------
__global__ void twmisc_kernel(const float* __restrict__ w1d, const float* __restrict__ wfc1,
                              const int* __restrict__ person_idx) {
    int bid = blockIdx.x;
    if (bid < CD) {
        int co = bid;
        for (int ci = threadIdx.x; ci < CD; ci += blockDim.x) {
            #pragma unroll
            for (int t = 0; t < 3; t++)
                g_BT1d[(size_t)co * K1D + t * CD + ci] =
                    __float2half(w1d[((size_t)co * CD + ci) * 3 + t]);
        }
    } else if (bid < CD + FC1DIM) {
        int n = bid - CD;
        for (int k = threadIdx.x; k < CD; k += blockDim.x)
            g_BTf1[(size_t)n * CD + k] = __float2half(wfc1[(size_t)k * FC1DIM + n]);
    } else {
        for (int r = threadIdx.x; r < BB * NN; r += blockDim.x)
            g_rowmap[r] = person_idx[r] * BB + (r >> 4);
    }
}

// ---------------- fused fmap-stage + roi align -> fp16 A of conv1 ----------------
#define ROI_CCHUNK 128
#define ROI_TSTRIDE 129
#define ROI_SMEM (SPAT * ROI_TSTRIDE * 4)   // 101136

__global__ void __launch_bounds__(256) roifused_kernel(
    const float* __restrict__ fmap, const float* __restrict__ boxes)
{
    extern __shared__ float tile[];          // [196][129]
    int b = blockIdx.y;
    int c0 = blockIdx.x * ROI_CCHUNK;
    int tid = threadIdx.x;

    const float* src = fmap + ((size_t)b * CC + c0) * SPAT;
    for (int i = tid; i < ROI_CCHUNK * SPAT; i += 256) {
        int c = i / SPAT, yx = i - c * SPAT;
        tile[yx * ROI_TSTRIDE + c] = src[(size_t)c * SPAT + yx];
    }
    __syncthreads();

    int c = tid & 127;
    int rg = tid >> 7;                       // 0 or 1: interleave rois
    for (int rr = rg; rr < NN + 1; rr += 2) {
        int s = (rr == 0) ? b : (BB + b * NN + (rr - 1));
        float x1, y1, x2, y2;
        if (rr == 0) { x1 = 0.f; y1 = 0.f; x2 = (float)FF; y2 = (float)FF; }
        else {
            const float* bx = boxes + (size_t)(b * NN + rr - 1) * 4;
            x1 = bx[0]; y1 = bx[1]; x2 = bx[2]; y2 = bx[3];
        }
        float rw = fmaxf(x2 - x1, 1.f), rh = fmaxf(y2 - y1, 1.f);
        float scy = rh / 3.0f, scx = rw / 3.0f;
        float wyv[6], wxv[6];
        int y0v[6], y1v[6], x0v[6], x1v[6];
        #pragma unroll
        for (int i = 0; i < 6; i++) {
            float pos = ((float)i + 0.5f) * 0.5f;
            float ys = fminf(fmaxf(y1 + pos * scy, 0.f), 13.f);
            float xs = fminf(fmaxf(x1 + pos * scx, 0.f), 13.f);
            float y0 = floorf(ys), x0 = floorf(xs);
            y0v[i] = (int)y0; x0v[i] = (int)x0;
            y1v[i] = min(y0v[i] + 1, 13); x1v[i] = min(x0v[i] + 1, 13);
            wyv[i] = ys - y0; wxv[i] = xs - x0;
        }
        float acc[9];
        #pragma unroll
        for (int k = 0; k < 9; k++) acc[k] = 0.f;
        #pragma unroll
        for (int sy = 0; sy < 6; sy++) {
            float wy = wyv[sy];
            int y0 = y0v[sy], y1 = y1v[sy];
            #pragma unroll
            for (int sx = 0; sx < 6; sx++) {
                float wx = wxv[sx];
                int x0 = x0v[sx], x1 = x1v[sx];
                float v00 = tile[(y0 * FF + x0) * ROI_TSTRIDE + c];
                float v01 = tile[(y0 * FF + x1) * ROI_TSTRIDE + c];
                float v10 = tile[(y1 * FF + x0) * ROI_TSTRIDE + c];
                float v11 = tile[(y1 * FF + x1) * ROI_TSTRIDE + c];
                float v = v00 * (1.f - wy) * (1.f - wx) + v01 * (1.f - wy) * wx
                        + v10 * wy * (1.f - wx) + v11 * wy * wx;
                acc[(sy >> 1) * 3 + (sx >> 1)] += v;
            }
        }
        #pragma unroll
        for (int k = 0; k < 9; k++)
            g_roiH[((size_t)s * 9 + k) * CC + c0 + c] = __float2half(acc[k] * 0.25f);
    }
}

// ---------------- fp16 tensor-core GEMM (mma.sync), persistent LPT tiles ----------------
#define MODE_CONV      0
#define MODE_BIAS      1
#define MODE_BIAS_RELU 2

#define ROW_B  144
#define STAGE_BYTES (128 * ROW_B)   // 18432
#define SMEM_A_OFF  0
#define SMEM_B_OFF  (3 * STAGE_BYTES)
#define SMEM_TOTAL  (6 * STAGE_BYTES)   // 110592

__device__ __forceinline__ void cpasync16(uint32_t dst, const void* src) {
    asm volatile("cp.async.cg.shared.global [%0], [%1], 16;\n" :: "r"(dst), "l"(src));
}

template<int MODE>
__global__ void __launch_bounds__(256, 2) gemm_f16(
    const __half* __restrict__ A, const __half* __restrict__ BT,
    __half* __restrict__ Cout, int N_, int K,
    const float* __restrict__ scale, const float* __restrict__ shift, int comask,
    int ntiles, int nbx, int ntpko, int cin_l2, const int* __restrict__ rowmap)
{
    extern __shared__ char smem[];
    __shared__ int s_kmap[10];
    uint32_t sbase;
    asm("{ .reg .u64 t; cvta.to.shared.u64 t, %1; cvt.u32.u64 %0, t; }" : "=r"(sbase) : "l"(smem));
    const int tid = threadIdx.x, lane = tid & 31, wid = tid >> 5;
    const int wm = wid >> 2, wn = wid & 3;
    const int G = gridDim.x;

    for (int which = 0; which < 2; which++) {
        int u;
        if (which == 0) {
            u = blockIdx.x;
        } else {
            u = 2 * G - 1 - blockIdx.x;
            if (u < G || u >= ntiles) break;
        }

        int m0, n0;
        __syncthreads();
        if (ntpko) {
            int gsz = ntpko * nbx;
            int g = u / gsz;
            int rem = u - g * gsz;
            int ko = c_korder[g];
            int by = rem / ntpko;
            int nx = rem - by * ntpko;
            m0 = by << 7;
            n0 = (ko * ntpko + nx) << 7;
            if (tid == 0) {
                int oy = ko / 3, ox = ko % 3;
                int nv = 0;
                #pragma unroll
                for (int kiy = 0; kiy < 3; kiy++)
                    #pragma unroll
                    for (int kix = 0; kix < 3; kix++) {
                        int ky = kiy - oy + 1, kx = kix - ox + 1;
                        if ((unsigned)ky < 3u && (unsigned)kx < 3u)
                            s_kmap[nv++] = kiy * 3 + kix;
                    }
                s_kmap[9] = nv << cin_l2;
            }
        } else {
            int by = u / nbx;
            m0 = by << 7;
            n0 = (u - by * nbx) << 7;
            if (tid == 0) s_kmap[9] = K >> 6;
        }
        __syncthreads();
        const int KT = s_kmap[9];

        const __half* baseA[4];
        const __half* baseB[4];
        uint32_t dstA[4], dstB[4];
        #pragma unroll
        for (int r = 0; r < 4; r++) {
            int q = tid + r * 256;
            int row = q >> 3, seg = q & 7;
            int gr = m0 + row;
            if (rowmap) gr = rowmap[gr];
            baseA[r] = A + (size_t)gr * K + seg * 8;
            baseB[r] = BT + (size_t)(n0 + row) * K + seg * 8;
            dstA[r] = sbase + SMEM_A_OFF + row * ROW_B + seg * 16;
            dstB[r] = sbase + SMEM_B_OFF + row * ROW_B + seg * 16;
        }

        float acc[4][4][4];
        #pragma unroll
        for (int mt = 0; mt < 4; mt++)
            #pragma unroll
            for (int nt = 0; nt < 4; nt++)
                #pragma unroll
                for (int i = 0; i < 4; i++) acc[mt][nt][i] = 0.f;

        auto stage = [&](int s) {
            int slot = s - (s / 3) * 3;
            int a_k0;
            if (ntpko) {
                int ki = s_kmap[s >> cin_l2];
                a_k0 = (ki << (cin_l2 + 6)) + ((s & ((1 << cin_l2) - 1)) << 6);
            } else {
                a_k0 = s << 6;
            }
            int b_k0 = s << 6;
            #pragma unroll
            for (int r = 0; r < 4; r++)
                cpasync16(dstA[r] + slot * STAGE_BYTES, baseA[r] + a_k0);
            #pragma unroll
            for (int r = 0; r < 4; r++)
                cpasync16(dstB[r] + slot * STAGE_BYTES, baseB[r] + b_k0);
            asm volatile("cp.async.commit_group;\n");
        };

        stage(0);
        if (KT > 1) stage(1);

        const int arow = wm * 64 + (lane & 15);
        uint32_t aAddrBase = sbase + SMEM_A_OFF + arow * ROW_B + (lane >> 4) * 16;
        const int brow = wn * 32 + ((lane >> 3) & 1) * 8 + (lane & 7);
        uint32_t bAddrBase = sbase + SMEM_B_OFF + brow * ROW_B + (lane >> 4) * 16;

        int slot = 0;
        for (int c = 0; c < KT; c++) {
            if (c == KT - 1) asm volatile("cp.async.wait_group 0;\n");
            else             asm volatile("cp.async.wait_group 1;\n");
            __syncthreads();
            if (c + 2 < KT) stage(c + 2);
            uint32_t aS = aAddrBase + slot * STAGE_BYTES;
            uint32_t bS = bAddrBase + slot * STAGE_BYTES;
            slot = (slot == 2) ? 0 : slot + 1;
            #pragma unroll
            for (int ks = 0; ks < 4; ks++) {
                uint32_t a[4][4], b[4][2];
                #pragma unroll
                for (int mt = 0; mt < 4; mt++) {
                    asm volatile("ldmatrix.sync.aligned.m8n8.x4.shared.b16 {%0,%1,%2,%3},[%4];"
                        : "=r"(a[mt][0]), "=r"(a[mt][1]), "=r"(a[mt][2]), "=r"(a[mt][3])
                        : "r"(aS + mt * 16 * ROW_B + ks * 32));
                }
                #pragma unroll
                for (int nt2 = 0; nt2 < 2; nt2++) {
                    uint32_t r0, r1, r2, r3;
                    asm volatile("ldmatrix.sync.aligned.m8n8.x4.shared.b16 {%0,%1,%2,%3},[%4];"
                        : "=r"(r0), "=r"(r1), "=r"(r2), "=r"(r3)
                        : "r"(bS + nt2 * 16 * ROW_B + ks * 32));
                    b[nt2 * 2 + 0][0] = r0; b[nt2 * 2 + 0][1] = r2;
                    b[nt2 * 2 + 1][0] = r1; b[nt2 * 2 + 1][1] = r3;
                }
                #pragma unroll
                for (int mt = 0; mt < 4; mt++)
                    #pragma unroll
                    for (int nt = 0; nt < 4; nt++)
                        asm volatile("mma.sync.aligned.m16n8k16.row.col.f32.f16.f16.f32 "
                            "{%0,%1,%2,%3},{%4,%5,%6,%7},{%8,%9},{%0,%1,%2,%3};"
                            : "+f"(acc[mt][nt][0]), "+f"(acc[mt][nt][1]),
                              "+f"(acc[mt][nt][2]), "+f"(acc[mt][nt][3])
                            : "r"(a[mt][0]), "r"(a[mt][1]), "r"(a[mt][2]), "r"(a[mt][3]),
                              "r"(b[nt][0]), "r"(b[nt][1]));
            }
        }

        #pragma unroll
        for (int mt = 0; mt < 4; mt++) {
            int r0 = m0 + wm * 64 + mt * 16 + (lane >> 2);
            #pragma unroll
            for (int nt = 0; nt < 4; nt++) {
                int c0 = n0 + wn * 32 + nt * 8 + (lane & 3) * 2;
                #pragma unroll
                for (int hh = 0; hh < 2; hh++) {
                    int rr = r0 + hh * 8;
                    float v0 = acc[mt][nt][hh * 2 + 0];
                    float v1 = acc[mt][nt][hh * 2 + 1];
                    if (MODE == MODE_CONV) {
                        int c0i = c0 & comask, c1i = (c0 + 1) & comask;
                        v0 = v0 * scale[c0i] + shift[c0i];
                        v1 = v1 * scale[c1i] + shift[c1i];
                        v0 = v0 > 0.f ? v0 : 0.1f * v0;
                        v1 = v1 > 0.f ? v1 : 0.1f * v1;
                    } else {
                        v0 += shift[c0];
                        v1 += shift[c0 + 1];
                        if (MODE == MODE_BIAS_RELU) { v0 = fmaxf(v0, 0.f); v1 = fmaxf(v1, 0.f); }
                    }
                    *(__half2*)(Cout + (size_t)rr * N_ + c0) = __floats2half2_rn(v0, v1);
                }
            }
        }
    }
}

// ---------------- scatter-add + im2col for conv1d (smem-staged) ----------------
#define BB_SMEM (17 * N2 * 2)   // 78336

__global__ void __launch_bounds__(256) buildbehavior_kernel(const int* __restrict__ person_idx) {
    extern __shared__ __half srows[];        // [17][N2]
    __shared__ int pid[NN];
    int b = blockIdx.y;
    int p0 = blockIdx.x * 5;
    int tid = threadIdx.x;
    if (tid < NN) pid[tid] = person_idx[b * NN + tid];

    const int row4 = N2 / 8;                 // float4s per row
    for (int i = tid; i < 17 * row4; i += 256) {
        int rr = i / row4, off = i - rr * row4;
        int gr = (rr == 0) ? b : (BB + b * NN + rr - 1);
        ((float4*)srows)[i] = ((const float4*)(g_out2h + (size_t)gr * N2))[off];
    }
    __syncthreads();

    for (int c = tid; c < CD; c += 256) {
        int col = (c % 9) * C2 + (c / 9);
        float g = __half2float(srows[col]);
        float v[NN];
        #pragma unroll
        for (int n = 0; n < NN; n++)
            v[n] = __half2float(srows[(1 + n) * N2 + col]);
        #pragma unroll
        for (int pi = 0; pi < 5; pi++) {
            int p = p0 + pi;
            float s = g;
            #pragma unroll
            for (int n = 0; n < NN; n++)
                if (pid[n] == p) s += v[n];
            __half hv = __float2half(s);
            size_t base = (size_t)(p * BB + b) * K1D;
            if (b + 1 < BB) g_A1d[(size_t)(p * BB + b + 1) * K1D + c] = hv;     // t=0
            g_A1d[base + CD + c] = hv;                                          // t=1
            if (b > 0) g_A1d[(size_t)(p * BB + b - 1) * K1D + 2 * CD + c] = hv; // t=2
            if (b == 0)      g_A1d[base + c] = __float2half(0.f);
            if (b == BB - 1) g_A1d[base + 2 * CD + c] = __float2half(0.f);
        }
    }
}

// ---------------- fc2 ----------------
__global__ void fc2_kernel(const float* __restrict__ w, const float* __restrict__ bias,
                           float* __restrict__ out) {
    __shared__ float red[4][32];
    int r = blockIdx.x;
    int t = threadIdx.x;
    int n = t & 31, kg = t >> 5;
    float acc = 0.f;
    if (n < NBCLS) {
        const __half* hr = g_hh + (size_t)r * FC1DIM + kg * 256;
        for (int j = 0; j < 256; j++)
            acc = fmaf(__half2float(hr[j]), w[(size_t)(kg * 256 + j) * NBCLS + n], acc);
    }
    red[kg][n] = acc;
    __syncthreads();
    if (kg == 0 && n < NBCLS)
        out[(size_t)r * NBCLS + n] = red[0][n] + red[1][n] + red[2][n] + red[3][n] + bias[n];
}

// ---------------- launch ----------------
extern "C" void kernel_launch(void* const* d_in, const int* in_sizes, int n_in,
                              void* d_out, int out_size) {
    const float* fmap      = (const float*)d_in[0];
    const float* boxes     = (const float*)d_in[1];
    const int*   person_idx= (const int*)  d_in[2];
    const float* conv1_w   = (const float*)d_in[3];
    const float* bn1_g     = (const float*)d_in[4];
    const float* bn1_b     = (const float*)d_in[5];
    const float* bn1_m     = (const float*)d_in[6];
    const float* bn1_v     = (const float*)d_in[7];
    const float* conv2_w   = (const float*)d_in[8];
    const float* bn2_g     = (const float*)d_in[9];
    const float* bn2_b     = (const float*)d_in[10];
    const float* bn2_m     = (const float*)d_in[11];
    const float* bn2_v     = (const float*)d_in[12];
    const float* conv1d_w  = (const float*)d_in[13];
    const float* conv1d_b  = (const float*)d_in[14];
    const float* fc1_w     = (const float*)d_in[15];
    const float* fc1_b     = (const float*)d_in[16];
    const float* fc2_w     = (const float*)d_in[17];
    const float* fc2_b     = (const float*)d_in[18];
    float* out = (float*)d_out;

    void *p_roiH, *p_BT1, *p_out1, *p_BT2, *p_out2, *p_A1d, *p_BT1d,
         *p_feats, *p_BTf1, *p_hh, *p_sc1, *p_sh1, *p_sc2, *p_sh2, *p_rowmap;
    cudaGetSymbolAddress(&p_roiH, g_roiH);
    cudaGetSymbolAddress(&p_BT1,  g_BT1);
    cudaGetSymbolAddress(&p_out1, g_out1h);
    cudaGetSymbolAddress(&p_BT2,  g_BT2);
    cudaGetSymbolAddress(&p_out2, g_out2h);
    cudaGetSymbolAddress(&p_A1d,  g_A1d);
    cudaGetSymbolAddress(&p_BT1d, g_BT1d);
    cudaGetSymbolAddress(&p_feats, g_feats);
    cudaGetSymbolAddress(&p_BTf1, g_BTf1);
    cudaGetSymbolAddress(&p_hh,   g_hh);
    cudaGetSymbolAddress(&p_sc1,  g_scale1);
    cudaGetSymbolAddress(&p_sh1,  g_shift1);
    cudaGetSymbolAddress(&p_sc2,  g_scale2);
    cudaGetSymbolAddress(&p_sh2,  g_shift2);
    cudaGetSymbolAddress(&p_rowmap, g_rowmap);

    static bool inited = false;
    static cudaStream_t s1, s2;
    static cudaEvent_t evFork, evW1, evW2;
    if (!inited) {
        inited = true;
        cudaStreamCreateWithFlags(&s1, cudaStreamNonBlocking);
        cudaStreamCreateWithFlags(&s2, cudaStreamNonBlocking);
        cudaEventCreateWithFlags(&evFork, cudaEventDisableTiming);
        cudaEventCreateWithFlags(&evW1, cudaEventDisableTiming);
        cudaEventCreateWithFlags(&evW2, cudaEventDisableTiming);
        cudaFuncSetAttribute(gemm_f16<MODE_CONV>,
                             cudaFuncAttributeMaxDynamicSharedMemorySize, SMEM_TOTAL);
        cudaFuncSetAttribute(gemm_f16<MODE_BIAS>,
                             cudaFuncAttributeMaxDynamicSharedMemorySize, SMEM_TOTAL);
        cudaFuncSetAttribute(gemm_f16<MODE_BIAS_RELU>,
                             cudaFuncAttributeMaxDynamicSharedMemorySize, SMEM_TOTAL);
        cudaFuncSetAttribute(roifused_kernel,
                             cudaFuncAttributeMaxDynamicSharedMemorySize, ROI_SMEM);
        cudaFuncSetAttribute(buildbehavior_kernel,
                             cudaFuncAttributeMaxDynamicSharedMemorySize, BB_SMEM);
    }

    // ---- launch 1: BN fold, then fork ----
    bnfold_kernel<<<3, 256>>>(bn1_g, bn1_b, bn1_m, bn1_v, bn2_g, bn2_b, bn2_m, bn2_v);
    cudaEventRecord(evFork, 0);
    cudaStreamWaitEvent(s1, evFork, 0);
    cudaStreamWaitEvent(s2, evFork, 0);

    // ---- launch 2: conv1 weight expand (side stream s1) ----
    expand_conv_w<CC, C1><<<N1, 256, 0, s1>>>(conv1_w, (__half*)p_BT1);
    cudaEventRecord(evW1, s1);

    // ---- launch 3: fused fmap-stage + roi align (main) ----
    roifused_kernel<<<dim3(CC / ROI_CCHUNK, BB), 256, ROI_SMEM>>>(fmap, boxes);

    // ---- launch 4: conv1 GEMM (main; waits on expand1) ----
    cudaStreamWaitEvent(0, evW1, 0);
    {
        int ntiles = (N1 / 128) * (S_PAD / 128);   // 324
        int grid = ntiles < GMAX ? ntiles : GMAX;  // 296
        gemm_f16<MODE_CONV><<<grid, 256, SMEM_TOTAL>>>(
            (const __half*)p_roiH, (const __half*)p_BT1, (__half*)p_out1,
            N1, K1, (const float*)p_sc1, (const float*)p_sh1, C1 - 1,
            ntiles, /*nby=*/S_PAD / 128, /*ntpko=*/C1 / 128, /*cin_l2=*/4, nullptr);
    }

    // ---- side stream s2: conv2 expand + merged small prep (overlaps conv1) ----
    expand_conv_w<C1, C2><<<N2, 256, 0, s2>>>(conv2_w, (__half*)p_BT2);
    twmisc_kernel<<<CD + FC1DIM + 1, 256, 0, s2>>>(conv1d_w, fc1_w, person_idx);
    cudaEventRecord(evW2, s2);

    // ---- conv2: waits on s2 prep ----
    cudaStreamWaitEvent(0, evW2, 0);
    {
        int ntiles = (N2 / 128) * (S_PAD / 128);   // 162
        gemm_f16<MODE_CONV><<<ntiles, 256, SMEM_TOTAL>>>(
            (const __half*)p_out1, (const __half*)p_BT2, (__half*)p_out2,
            N2, K2, (const float*)p_sc2, (const float*)p_sh2, C2 - 1,
            ntiles, /*nby=*/S_PAD / 128, /*ntpko=*/C2 / 128, /*cin_l2=*/3, nullptr);
    }

    // ---- scatter-add + im2col (smem-staged) ----
    buildbehavior_kernel<<<dim3(PP / 5, BB), 256, BB_SMEM>>>(person_idx);

    // ---- conv1d: M=1024 gathered rows, N=2304, K=6912 -> writes g_feats ----
    {
        int ntiles = (CD / 128) * ((BB * NN) / 128);   // 144
        gemm_f16<MODE_BIAS><<<ntiles, 256, SMEM_TOTAL>>>(
            (const __half*)p_A1d, (const __half*)p_BT1d, (__half*)p_feats,
            CD, K1D, nullptr, conv1d_b, 0,
            ntiles, /*nbx=*/CD / 128, 0, 0, (const int*)p_rowmap);
    }

    // ---- fc1: M=1024, N=1024, K=2304 ----
    {
        int ntiles = (FC1DIM / 128) * ((BB * NN) / 128);   // 64
        gemm_f16<MODE_BIAS_RELU><<<ntiles, 256, SMEM_TOTAL>>>(
            (const __half*)p_feats, (const __half*)p_BTf1, (__half*)p_hh,
            FC1DIM, CD, nullptr, fc1_b, 0,
            ntiles, /*nbx=*/FC1DIM / 128, 0, 0, nullptr);
    }

    // ---- fc2 -> output ----
    fc2_kernel<<<BB * NN, 128>>>(fc2_w, fc2_b, out);
}